// round 11
// baseline (speedup 1.0000x reference)
#include <cuda_runtime.h>
#include <math.h>
#include <stdint.h>

#define B_  2
#define T_  2048
#define C_  1024
#define H_  16
#define D_  64
#define BH_ 32
#define M_  4096
#define N3_ 3072
#define K_  1024
#define KP_ 512        // packed k-pairs per row

// ---------------- scratch (__device__ globals; no allocs allowed) -----------
// Everything packed as bf16 hi/lo pair-words (pair along k / d).
__device__ uint32_t g_xp_h[M_*KP_],  g_xp_l[M_*KP_];    // x   [m][kp]
__device__ uint32_t g_wqp_h[N3_*KP_], g_wqp_l[N3_*KP_]; // wqkv^T [n][kp]
__device__ uint32_t g_wpp_h[C_*KP_],  g_wpp_l[C_*KP_];  // wproj^T [n][kp]
__device__ uint32_t g_yp_h[M_*KP_],  g_yp_l[M_*KP_];    // attn out [m][kp]
__device__ uint32_t g_qp_h[BH_*T_*32], g_qp_l[BH_*T_*32];
__device__ uint32_t g_kp_h[BH_*T_*32], g_kp_l[BH_*T_*32];
__device__ uint32_t g_vp_h[BH_*T_*32], g_vp_l[BH_*T_*32];
__device__ float g_cos[T_*32], g_sin[T_*32];

// ---------------- helpers ----------------------------------------------------
__device__ __forceinline__ uint32_t smem_u32(const void* p) {
    uint32_t a;
    asm("{ .reg .u64 t; cvta.to.shared.u64 t, %1; cvt.u32.u64 %0, t; }"
        : "=r"(a) : "l"(p));
    return a;
}

// split two fp32 into packed bf16 hi-pair and lo-pair (v0 -> low half)
__device__ __forceinline__ void split2bf(float v0, float v1,
                                         uint32_t& h, uint32_t& l) {
    uint32_t hp;
    asm("cvt.rn.bf16x2.f32 %0, %1, %2;" : "=r"(hp) : "f"(v1), "f"(v0));
    float h0 = __uint_as_float(hp << 16);
    float h1 = __uint_as_float(hp & 0xFFFF0000u);
    float r0 = v0 - h0;
    float r1 = v1 - h1;
    asm("cvt.rn.bf16x2.f32 %0, %1, %2;" : "=r"(l) : "f"(r1), "f"(r0));
    h = hp;
}

__device__ __forceinline__ uint32_t prmt(uint32_t a, uint32_t b, uint32_t sel) {
    uint32_t r;
    asm("prmt.b32 %0, %1, %2, %3;" : "=r"(r) : "r"(a), "r"(b), "r"(sel));
    return r;
}

__device__ __forceinline__ void mma_bf16(float c[4], const uint32_t a[4],
                                         const uint32_t b[2]) {
    asm volatile(
        "mma.sync.aligned.m16n8k16.row.col.f32.bf16.bf16.f32 "
        "{%0,%1,%2,%3}, {%4,%5,%6,%7}, {%8,%9}, {%0,%1,%2,%3};"
        : "+f"(c[0]), "+f"(c[1]), "+f"(c[2]), "+f"(c[3])
        : "r"(a[0]), "r"(a[1]), "r"(a[2]), "r"(a[3]), "r"(b[0]), "r"(b[1]));
}

// fast exp2 on FMA/ALU pipes (no MUFU)
__device__ __forceinline__ float fexp2(float t) {
    t = fmaxf(t, -126.0f);
    float r = t + 12582912.0f;
    int   n = __float_as_int(r);
    float f = t - (r - 12582912.0f);
    float p = 1.33335581e-3f;
    p = fmaf(p, f, 9.61812911e-3f);
    p = fmaf(p, f, 5.55041087e-2f);
    p = fmaf(p, f, 2.40226507e-1f);
    p = fmaf(p, f, 6.93147180e-1f);
    p = fmaf(p, f, 1.0f);
    return __int_as_float(__float_as_int(p) + (n << 23));
}
#define L2E_ 1.4426950408889634f

__device__ __forceinline__ void cpa16(uint32_t s, const void* gp) {
    asm volatile("cp.async.cg.shared.global [%0], [%1], 16;" :: "r"(s), "l"(gp));
}
#define CP_COMMIT() asm volatile("cp.async.commit_group;" ::: "memory")
#define CP_WAIT1()  asm volatile("cp.async.wait_group 1;" ::: "memory")
#define CP_WAIT2()  asm volatile("cp.async.wait_group 2;" ::: "memory")

// ---------------- RoPE table -------------------------------------------------
__global__ void rope_table_kernel() {
    int idx = blockIdx.x * 256 + threadIdx.x;   // 65536
    int t = idx >> 5, i = idx & 31;
    double inv = pow(10000.0, -(double)(2 * i) / 64.0);
    float ff = (float)t * (float)inv;
    double s, c;
    sincos((double)ff, &s, &c);
    g_cos[idx] = (float)c;
    g_sin[idx] = (float)s;
}

// ---------------- converters -------------------------------------------------
__global__ __launch_bounds__(256) void convert_x_kernel(const float* __restrict__ x) {
    int i = blockIdx.x * 256 + threadIdx.x;     // over M_*K_/4 float4s
    float4 v = ((const float4*)x)[i];
    uint2 h, l;
    split2bf(v.x, v.y, h.x, l.x);
    split2bf(v.z, v.w, h.y, l.y);
    ((uint2*)g_xp_h)[i] = h;
    ((uint2*)g_xp_l)[i] = l;
}

// W[K][N] fp32 -> out[N][KP_] packed bf16 hi/lo pair-words along k.
// WHICH selects the destination INSIDE device code (host-side __device__
// symbol arguments resolve to host shadow addresses -- the R4/R10 bug).
template <int WHICH>
__global__ __launch_bounds__(256) void transpose_split_kernel(
    const float* __restrict__ W, int N)
{
    uint32_t* __restrict__ oh = WHICH ? g_wpp_h : g_wqp_h;
    uint32_t* __restrict__ ol = WHICH ? g_wpp_l : g_wqp_l;
    __shared__ float tile[32][33];
    __shared__ uint32_t obh[32][17], obl[32][17];
    const int n0 = blockIdx.x * 32, k0 = blockIdx.y * 32;
    const int tx = threadIdx.x, ty = threadIdx.y;   // (32, 8)
    #pragma unroll
    for (int j = 0; j < 32; j += 8)
        tile[ty + j][tx] = W[(size_t)(k0 + ty + j) * N + n0 + tx];
    __syncthreads();
    #pragma unroll
    for (int j = 0; j < 2; j++) {
        int kp = ty + 8 * j;                        // 0..15
        uint32_t h, l;
        split2bf(tile[2 * kp][tx], tile[2 * kp + 1][tx], h, l);
        obh[tx][kp] = h; obl[tx][kp] = l;
    }
    __syncthreads();
    const int c = ty * 32 + tx;                     // 0..255
    const int arr = c >> 7, idx = c & 127;
    const int row = idx >> 2, ch = (idx & 3) * 4;
    uint32_t (*ob)[17] = arr ? obl : obh;
    uint4 v = make_uint4(ob[row][ch], ob[row][ch + 1],
                         ob[row][ch + 2], ob[row][ch + 3]);
    uint32_t* dst = arr ? ol : oh;
    *(uint4*)(dst + (size_t)(n0 + row) * KP_ + (k0 >> 1) + ch) = v;
}

// ---------------- packed-bf16 GEMM: pure LDS + HMMA mainloop ----------------
#define GSTR 12                         // words/row: 8 data + 4 pad (conflict-free)
#define GT_W (128 * GSTR)               // 1536 words per array tile
#define STG_W (4 * GT_W)                // Ah, Al, Bh, Bl = 6144 words/stage
#define NSTAGE 4
#define GEMM_SMEM_BYTES (NSTAGE * STG_W * 4)   // 98,304 B

__device__ __forceinline__ void gemm_load_stage(
    uint32_t su, const uint32_t* __restrict__ Aph, const uint32_t* __restrict__ Apl,
    const uint32_t* __restrict__ Bph, const uint32_t* __restrict__ Bpl,
    int m0, int n0, int j, int tid)
{
    const int row = tid >> 1, ch = (tid & 1) * 4;
    const size_t ga = (size_t)(m0 + row) * KP_ + j * 8 + ch;
    const size_t gb = (size_t)(n0 + row) * KP_ + j * 8 + ch;
    const uint32_t so = (row * GSTR + ch) * 4;
    cpa16(su + so,                 Aph + ga);
    cpa16(su + GT_W * 4 + so,      Apl + ga);
    cpa16(su + 2 * GT_W * 4 + so,  Bph + gb);
    cpa16(su + 3 * GT_W * 4 + so,  Bpl + gb);
}

template <int MODE>
__global__ __launch_bounds__(256, 2) void gemm_bf16(
    const float* __restrict__ bias, float* __restrict__ out)
{
    extern __shared__ uint32_t dsm[];
    const uint32_t sb = smem_u32(dsm);

    // device-side symbols (host-side would give host shadow addresses)
    const uint32_t* Aph = MODE ? g_yp_h : g_xp_h;
    const uint32_t* Apl = MODE ? g_yp_l : g_xp_l;
    const uint32_t* Bph = MODE ? g_wpp_h : g_wqp_h;
    const uint32_t* Bpl = MODE ? g_wpp_l : g_wqp_l;

    const int tid  = threadIdx.x;
    const int wid  = tid >> 5;
    const int lane = tid & 31;
    const int g  = lane >> 2;
    const int tq = lane & 3;
    const int wm = wid >> 2;
    const int wn = wid & 3;
    const int m0 = blockIdx.y * 128;
    const int n0 = blockIdx.x * 128;

    float acc[4][4][4] = {};

    gemm_load_stage(sb, Aph, Apl, Bph, Bpl, m0, n0, 0, tid);  CP_COMMIT();
    gemm_load_stage(sb + STG_W * 4, Aph, Apl, Bph, Bpl, m0, n0, 1, tid);  CP_COMMIT();
    gemm_load_stage(sb + 2 * STG_W * 4, Aph, Apl, Bph, Bpl, m0, n0, 2, tid);  CP_COMMIT();

    for (int j = 0; j < K_ / 16; j++) {
        CP_WAIT2();
        __syncthreads();
        if (j + 3 < K_ / 16)
            gemm_load_stage(sb + (uint32_t)((j + 3) & 3) * STG_W * 4,
                            Aph, Apl, Bph, Bpl, m0, n0, j + 3, tid);
        CP_COMMIT();

        const uint32_t* Ah = dsm + (j & 3) * STG_W;
        const uint32_t* Al = Ah + GT_W;
        const uint32_t* Bh = Ah + 2 * GT_W;
        const uint32_t* Bl = Ah + 3 * GT_W;

        uint32_t ah[4][4], al[4][4], bh[4][2], bl[4][2];
        #pragma unroll
        for (int mi = 0; mi < 4; mi++) {
            int mb = wm * 64 + mi * 16 + g;
            ah[mi][0] = Ah[mb * GSTR + tq];
            ah[mi][1] = Ah[(mb + 8) * GSTR + tq];
            ah[mi][2] = Ah[mb * GSTR + tq + 4];
            ah[mi][3] = Ah[(mb + 8) * GSTR + tq + 4];
            al[mi][0] = Al[mb * GSTR + tq];
            al[mi][1] = Al[(mb + 8) * GSTR + tq];
            al[mi][2] = Al[mb * GSTR + tq + 4];
            al[mi][3] = Al[(mb + 8) * GSTR + tq + 4];
        }
        #pragma unroll
        for (int ni = 0; ni < 4; ni++) {
            int nb = wn * 32 + ni * 8 + g;
            bh[ni][0] = Bh[nb * GSTR + tq];
            bh[ni][1] = Bh[nb * GSTR + tq + 4];
            bl[ni][0] = Bl[nb * GSTR + tq];
            bl[ni][1] = Bl[nb * GSTR + tq + 4];
        }
        #pragma unroll
        for (int mi = 0; mi < 4; mi++)
            #pragma unroll
            for (int ni = 0; ni < 4; ni++) {
                mma_bf16(acc[mi][ni], ah[mi], bh[ni]);
                mma_bf16(acc[mi][ni], al[mi], bh[ni]);
                mma_bf16(acc[mi][ni], ah[mi], bl[ni]);
            }
    }

    // ------------- epilogue -------------
    #pragma unroll
    for (int mi = 0; mi < 4; mi++) {
        #pragma unroll
        for (int ni = 0; ni < 4; ni++) {
            const float* c = acc[mi][ni];
            int r0 = m0 + wm * 64 + mi * 16 + g;
            int nc = n0 + wn * 32 + ni * 8 + 2 * tq;
            #pragma unroll
            for (int half = 0; half < 2; half++) {
                int m = r0 + half * 8;
                float e = c[half * 2 + 0];
                float o = c[half * 2 + 1];
                if (MODE == 0) {
                    int b = m >> 11, t = m & 2047;
                    int sec = nc >> 10, cc = nc & 1023;
                    int hd = cc >> 6, d = cc & 63;       // d even
                    size_t idx = ((size_t)((b << 4) + hd) * T_ + t) * 32 + (d >> 1);
                    uint32_t ph, pl;
                    if (sec == 2) {
                        split2bf(e, o, ph, pl);
                        g_vp_h[idx] = ph; g_vp_l[idx] = pl;
                    } else {
                        float co = g_cos[t * 32 + (d >> 1)];
                        float si = g_sin[t * 32 + (d >> 1)];
                        float oe = e * co - o * si;
                        float oo = e * si + o * co;
                        if (sec == 0) {
                            split2bf(oe * 0.125f, oo * 0.125f, ph, pl);
                            g_qp_h[idx] = ph; g_qp_l[idx] = pl;
                        } else {
                            split2bf(oe, oo, ph, pl);
                            g_kp_h[idx] = ph; g_kp_l[idx] = pl;
                        }
                    }
                } else {
                    float2 bv = *(const float2*)(bias + nc);
                    *(float2*)(out + (size_t)m * C_ + nc) =
                        make_float2(e + bv.x, o + bv.y);
                }
            }
        }
    }
}

// ---------------- MMA flash attention (pre-split bf16, repacked V) ----------
#define KPSTR 36
#define KPW   (64 * KPSTR)                 // 2304 words per array
#define VRSTR 36
#define VRW   (64 * VRSTR)
#define ASTG_W (2 * KPW + 2 * VRW)         // 9216 words per stage
#define VP_BASE (2 * ASTG_W)               // 18432
#define VPSTG_W (2 * KPW)                  // 4608 per Vp stage (hi+lo)
#define ATTN_WORDS (VP_BASE + 2 * VPSTG_W) // 27648
#define ATTN_SMEM_B (ATTN_WORDS * 4)       // 110,592 B

__device__ __forceinline__ void attn_load_stage(
    uint32_t su, const uint32_t* __restrict__ kph,
    const uint32_t* __restrict__ kpl, const uint32_t* __restrict__ vph,
    const uint32_t* __restrict__ vpl, int kv0, int tid)
{
    #pragma unroll
    for (int i = 0; i < 2; i++) {    // Kp hi: 64 rows x 32 words
        int c = i * 256 + tid;
        int r = c >> 3, ch = (c & 7) * 4;
        cpa16(su + (r * KPSTR + ch) * 4, kph + (size_t)(kv0 + r) * 32 + ch);
    }
    #pragma unroll
    for (int i = 0; i < 2; i++) {    // Kp lo
        int c = i * 256 + tid;
        int r = c >> 3, ch = (c & 7) * 4;
        cpa16(su + (KPW + r * KPSTR + ch) * 4, kpl + (size_t)(kv0 + r) * 32 + ch);
    }
    #pragma unroll
    for (int i = 0; i < 2; i++) {    // V raw hi (packed along d)
        int c = i * 256 + tid;
        int r = c >> 3, ch = (c & 7) * 4;
        cpa16(su + (2 * KPW + r * VRSTR + ch) * 4, vph + (size_t)(kv0 + r) * 32 + ch);
    }
    #pragma unroll
    for (int i = 0; i < 2; i++) {    // V raw lo
        int c = i * 256 + tid;
        int r = c >> 3, ch = (c & 7) * 4;
        cpa16(su + (2 * KPW + VRW + r * VRSTR + ch) * 4, vpl + (size_t)(kv0 + r) * 32 + ch);
    }
}

__global__ __launch_bounds__(256, 2) void attn_mma() {
    extern __shared__ uint32_t sw[];
    const uint32_t sb = smem_u32(sw);
    const int tid  = threadIdx.x;
    const int wid  = tid >> 5, lane = tid & 31;
    const int g    = lane >> 2, tq = lane & 3;
    const int qt   = (int)gridDim.x - 1 - (int)blockIdx.x;  // heavy-first
    const int bh   = blockIdx.y;
    const int q0   = qt * 128;

    const uint32_t* kph = g_kp_h + (size_t)bh * T_ * 32;
    const uint32_t* kpl = g_kp_l + (size_t)bh * T_ * 32;
    const uint32_t* vph = g_vp_h + (size_t)bh * T_ * 32;
    const uint32_t* vpl = g_vp_l + (size_t)bh * T_ * 32;

    // ---- Q fragments straight from packed gmem (no conversion at all) ----
    const int wrow0 = q0 + wid * 16;
    uint32_t qh[4][4], ql[4][4];
    {
        const size_t r0 = ((size_t)bh * T_ + wrow0 + g) * 32;
        const size_t r8 = r0 + 8 * 32;
        #pragma unroll
        for (int ks = 0; ks < 4; ks++) {
            int cp0 = 8 * ks + tq;
            qh[ks][0] = g_qp_h[r0 + cp0];     ql[ks][0] = g_qp_l[r0 + cp0];
            qh[ks][1] = g_qp_h[r8 + cp0];     ql[ks][1] = g_qp_l[r8 + cp0];
            qh[ks][2] = g_qp_h[r0 + cp0 + 4]; ql[ks][2] = g_qp_l[r0 + cp0 + 4];
            qh[ks][3] = g_qp_h[r8 + cp0 + 4]; ql[ks][3] = g_qp_l[r8 + cp0 + 4];
        }
    }

    float accO[8][4] = {};
    float mrow[2] = {-1e30f, -1e30f};
    float lrow[2] = {0.0f, 0.0f};
    const int nkv = 2 * qt + 2;
    const int xorv = (g >> 1) & 3;

    attn_load_stage(sb, kph, kpl, vph, vpl, 0, tid);  CP_COMMIT();
    if (nkv > 1) attn_load_stage(sb + ASTG_W * 4, kph, kpl, vph, vpl, 64, tid);
    CP_COMMIT();

    for (int j = 0; j < nkv; j++) {
        const int s = j & 1;
        const int kv0 = j * 64;
        const uint32_t* Kh = sw + s * ASTG_W;
        const uint32_t* Kl = Kh + KPW;
        const uint32_t* Vr_h = Kh + 2 * KPW;
        const uint32_t* Vr_l = Vr_h + VRW;
        uint32_t* Vp_h = sw + VP_BASE + s * VPSTG_W;
        uint32_t* Vp_l = Vp_h + KPW;

        CP_WAIT1();
        __syncthreads();

        // ---- cooperative V repack: Vp[d][kvp ^ (dw&3)] via PRMT ----
        {
            const int dw = (lane >> 3) + 4 * wid;       // 0..31
            #pragma unroll
            for (int i = 0; i < 4; i++) {
                int kvp = (lane & 7) + 8 * i;
                int c = kvp ^ (dw & 3);
                uint32_t w0 = Vr_h[(2 * kvp) * VRSTR + dw];
                uint32_t w1 = Vr_h[(2 * kvp + 1) * VRSTR + dw];
                Vp_h[(2 * dw) * KPSTR + c]     = prmt(w0, w1, 0x5410);
                Vp_h[(2 * dw + 1) * KPSTR + c] = prmt(w0, w1, 0x7632);
                w0 = Vr_l[(2 * kvp) * VRSTR + dw];
                w1 = Vr_l[(2 * kvp + 1) * VRSTR + dw];
                Vp_l[(2 * dw) * KPSTR + c]     = prmt(w0, w1, 0x5410);
                Vp_l[(2 * dw + 1) * KPSTR + c] = prmt(w0, w1, 0x7632);
            }
        }
        __syncthreads();

        if (kv0 <= wrow0 + 15) {
            // ---- S = Q @ K^T (K frags: pure LDS) ----
            float accS[8][4] = {};
            #pragma unroll
            for (int ks = 0; ks < 4; ks++) {
                const int cp = 8 * ks + tq;
                #pragma unroll
                for (int nf = 0; nf < 8; nf++) {
                    const int nb = nf * 8 + g;
                    uint32_t kh[2], kl[2];
                    kh[0] = Kh[nb * KPSTR + cp];     kl[0] = Kl[nb * KPSTR + cp];
                    kh[1] = Kh[nb * KPSTR + cp + 4]; kl[1] = Kl[nb * KPSTR + cp + 4];
                    mma_bf16(accS[nf], qh[ks], kh);
                    mma_bf16(accS[nf], ql[ks], kh);
                    mma_bf16(accS[nf], qh[ks], kl);
                }
            }

            // ---- causal mask ----
            if (kv0 + 63 > wrow0) {
                #pragma unroll
                for (int nf = 0; nf < 8; nf++)
                    #pragma unroll
                    for (int r = 0; r < 4; r++) {
                        int row = wrow0 + g + (r >> 1) * 8;
                        int col = kv0 + nf * 8 + 2 * tq + (r & 1);
                        if (col > row) accS[nf][r] = -1e30f;
                    }
            }

            // ---- online softmax (fexp2, no MUFU) ----
            #pragma unroll
            for (int hh = 0; hh < 2; hh++) {
                float mx = -1e30f;
                #pragma unroll
                for (int nf = 0; nf < 8; nf++)
                    mx = fmaxf(mx, fmaxf(accS[nf][2*hh], accS[nf][2*hh+1]));
                mx = fmaxf(mx, __shfl_xor_sync(0xffffffffu, mx, 1));
                mx = fmaxf(mx, __shfl_xor_sync(0xffffffffu, mx, 2));
                float mn = fmaxf(mrow[hh], mx);
                float corr = fexp2((mrow[hh] - mn) * L2E_);
                mrow[hh] = mn;
                float mnL = mn * L2E_;
                float ps = 0.0f;
                #pragma unroll
                for (int nf = 0; nf < 8; nf++) {
                    float p0 = fexp2(fmaf(accS[nf][2*hh],   L2E_, -mnL));
                    float p1 = fexp2(fmaf(accS[nf][2*hh+1], L2E_, -mnL));
                    accS[nf][2*hh] = p0; accS[nf][2*hh+1] = p1;
                    ps += p0 + p1;
                }
                ps += __shfl_xor_sync(0xffffffffu, ps, 1);
                ps += __shfl_xor_sync(0xffffffffu, ps, 2);
                lrow[hh] = lrow[hh] * corr + ps;
                #pragma unroll
                for (int nf = 0; nf < 8; nf++) {
                    accO[nf][2*hh]   *= corr;
                    accO[nf][2*hh+1] *= corr;
                }
            }

            // ---- O += P @ V : P frags from accS regs, V frags pure LDS ----
            #pragma unroll
            for (int ks = 0; ks < 4; ks++) {
                uint32_t ph[4], pl[4];
                split2bf(accS[2*ks][0],   accS[2*ks][1],   ph[0], pl[0]);
                split2bf(accS[2*ks][2],   accS[2*ks][3],   ph[1], pl[1]);
                split2bf(accS[2*ks+1][0], accS[2*ks+1][1], ph[2], pl[2]);
                split2bf(accS[2*ks+1][2], accS[2*ks+1][3], ph[3], pl[3]);
                const int c0 = (8 * ks + tq) ^ xorv;
                const int c1 = (8 * ks + tq + 4) ^ xorv;
                #pragma unroll
                for (int nf = 0; nf < 8; nf++) {
                    const int nb = nf * 8 + g;
                    uint32_t vh[2], vl[2];
                    vh[0] = Vp_h[nb * KPSTR + c0]; vl[0] = Vp_l[nb * KPSTR + c0];
                    vh[1] = Vp_h[nb * KPSTR + c1]; vl[1] = Vp_l[nb * KPSTR + c1];
                    mma_bf16(accO[nf], ph, vh);
                    mma_bf16(accO[nf], pl, vh);
                    mma_bf16(accO[nf], ph, vl);
                }
            }
        }
        __syncthreads();   // all reads of raw stage s done before refill

        if (j + 2 < nkv)
            attn_load_stage(sb + (uint32_t)s * ASTG_W * 4, kph, kpl, vph, vpl,
                            kv0 + 128, tid);
        CP_COMMIT();
    }

    // ---- write y packed [m][kp] hi/lo (feeds proj GEMM directly) ----
    const int b = bh >> 4, hd = bh & 15;
    #pragma unroll
    for (int hh = 0; hh < 2; hh++) {
        float inv = 1.0f / lrow[hh];
        int t = q0 + wid * 16 + g + hh * 8;
        size_t rowbase = (size_t)(b * T_ + t) * KP_ + hd * 32;
        #pragma unroll
        for (int nf = 0; nf < 8; nf++) {
            uint32_t ph, pl;
            split2bf(accO[nf][2*hh] * inv, accO[nf][2*hh+1] * inv, ph, pl);
            g_yp_h[rowbase + nf * 4 + tq] = ph;
            g_yp_l[rowbase + nf * 4 + tq] = pl;
        }
    }
}

// ---------------------------------------------------------------------------
extern "C" void kernel_launch(void* const* d_in, const int* in_sizes, int n_in,
                              void* d_out, int out_size)
{
    const float* x      = (const float*)d_in[0];
    const float* w_qkv  = (const float*)d_in[1];
    const float* w_proj = (const float*)d_in[2];
    const float* b_proj = (const float*)d_in[3];
    float* out = (float*)d_out;
    (void)in_sizes; (void)n_in; (void)out_size;

    cudaFuncSetAttribute(gemm_bf16<0>,
                         cudaFuncAttributeMaxDynamicSharedMemorySize, GEMM_SMEM_BYTES);
    cudaFuncSetAttribute(gemm_bf16<1>,
                         cudaFuncAttributeMaxDynamicSharedMemorySize, GEMM_SMEM_BYTES);
    cudaFuncSetAttribute(attn_mma,
                         cudaFuncAttributeMaxDynamicSharedMemorySize, ATTN_SMEM_B);

    rope_table_kernel<<<256, 256>>>();
    convert_x_kernel<<<M_ * K_ / 4 / 256, 256>>>(x);
    transpose_split_kernel<0><<<dim3(N3_/32, K_/32), dim3(32, 8)>>>(w_qkv, N3_);
    transpose_split_kernel<1><<<dim3(C_/32,  K_/32), dim3(32, 8)>>>(w_proj, C_);
    gemm_bf16<0><<<dim3(N3_ / 128, M_ / 128), 256, GEMM_SMEM_BYTES>>>(nullptr, nullptr);
    attn_mma<<<dim3(T_ / 128, BH_), 256, ATTN_SMEM_B>>>();
    gemm_bf16<1><<<dim3(C_ / 128, M_ / 128), 256, GEMM_SMEM_BYTES>>>(b_proj, out);
}

// round 12
// speedup vs baseline: 1.4081x; 1.4081x over previous
#include <cuda_runtime.h>
#include <cuda_fp16.h>
#include <math.h>
#include <stdint.h>

#define B_  2
#define T_  2048
#define C_  1024
#define H_  16
#define D_  64
#define BH_ 32
#define M_  4096
#define N3_ 3072
#define K_  1024

// ---------------- scratch (__device__ globals; no allocs allowed) -----------
// q: fp16 hi/lo packed d-pair words; k, v: single fp16 packed (2-pass residual
// lives on the A-operand side only). y: raw fp32 (proj splits at frag load).
__device__ uint32_t g_qp_h[BH_*T_*32], g_qp_l[BH_*T_*32];
__device__ uint32_t g_kp[BH_*T_*32];
__device__ uint32_t g_vp[BH_*T_*32];
__device__ float g_y[M_*C_];
__device__ float g_cos[T_*32], g_sin[T_*32];

// ---------------- helpers ----------------------------------------------------
__device__ __forceinline__ uint32_t smem_u32(const void* p) {
    uint32_t a;
    asm("{ .reg .u64 t; cvta.to.shared.u64 t, %1; cvt.u32.u64 %0, t; }"
        : "=r"(a) : "l"(p));
    return a;
}

// pack two fp32 into f16x2 (v0 -> low half)
__device__ __forceinline__ uint32_t cvt2h(float v0, float v1) {
    uint32_t r;
    asm("cvt.rn.f16x2.f32 %0, %1, %2;" : "=r"(r) : "f"(v1), "f"(v0));
    return r;
}

// split two fp32 into f16x2 hi-pair and f16x2 lo-pair (residuals)
__device__ __forceinline__ void split2h(float v0, float v1,
                                        uint32_t& h, uint32_t& l) {
    h = cvt2h(v0, v1);
    float h0, h1;
    asm("{ .reg .f16 lo, hi; mov.b32 {lo, hi}, %2;"
        "  cvt.f32.f16 %0, lo; cvt.f32.f16 %1, hi; }"
        : "=f"(h0), "=f"(h1) : "r"(h));
    l = cvt2h(v0 - h0, v1 - h1);
}

__device__ __forceinline__ uint32_t prmt(uint32_t a, uint32_t b, uint32_t sel) {
    uint32_t r;
    asm("prmt.b32 %0, %1, %2, %3;" : "=r"(r) : "r"(a), "r"(b), "r"(sel));
    return r;
}

__device__ __forceinline__ void mma_f16(float c[4], const uint32_t a[4],
                                        const uint32_t b[2]) {
    asm volatile(
        "mma.sync.aligned.m16n8k16.row.col.f32.f16.f16.f32 "
        "{%0,%1,%2,%3}, {%4,%5,%6,%7}, {%8,%9}, {%0,%1,%2,%3};"
        : "+f"(c[0]), "+f"(c[1]), "+f"(c[2]), "+f"(c[3])
        : "r"(a[0]), "r"(a[1]), "r"(a[2]), "r"(a[3]), "r"(b[0]), "r"(b[1]));
}

// fast exp2 on FMA/ALU pipes (no MUFU)
__device__ __forceinline__ float fexp2(float t) {
    t = fmaxf(t, -126.0f);
    float r = t + 12582912.0f;
    int   n = __float_as_int(r);
    float f = t - (r - 12582912.0f);
    float p = 1.33335581e-3f;
    p = fmaf(p, f, 9.61812911e-3f);
    p = fmaf(p, f, 5.55041087e-2f);
    p = fmaf(p, f, 2.40226507e-1f);
    p = fmaf(p, f, 6.93147180e-1f);
    p = fmaf(p, f, 1.0f);
    return __int_as_float(__float_as_int(p) + (n << 23));
}
#define L2E_ 1.4426950408889634f

__device__ __forceinline__ void cpa16(uint32_t s, const void* gp) {
    asm volatile("cp.async.cg.shared.global [%0], [%1], 16;" :: "r"(s), "l"(gp));
}
#define CP_COMMIT() asm volatile("cp.async.commit_group;" ::: "memory")
#define CP_WAIT1()  asm volatile("cp.async.wait_group 1;" ::: "memory")

// ---------------- RoPE table -------------------------------------------------
__global__ void rope_table_kernel() {
    int idx = blockIdx.x * 256 + threadIdx.x;   // 65536
    int t = idx >> 5, i = idx & 31;
    double inv = pow(10000.0, -(double)(2 * i) / 64.0);
    float ff = (float)t * (float)inv;
    double s, c;
    sincos((double)ff, &s, &c);
    g_cos[idx] = (float)c;
    g_sin[idx] = (float)s;
}

// ---------------- fp16 2-pass GEMM (R9 structure: raw fp32 smem) ------------
#define ASTR 36                       // A smem row stride
#define AS_W (128 * ASTR)             // 4608 words
#define BSTR 132                      // B smem row stride
#define BS_W (32 * BSTR)              // 4224 words
#define STG_W (AS_W + BS_W)           // 8832 words / stage
#define GEMM_SMEM_BYTES (2 * STG_W * 4)  // 70,656 B

__device__ __forceinline__ void gemm_load_stage(
    uint32_t su, const float* __restrict__ A, const float* __restrict__ W,
    int m0, int n0, int kk, int N, int tid)
{
    const uint32_t bu = su + AS_W * 4;
    #pragma unroll
    for (int i = 0; i < 4; i++) {               // A: 128m x 32k, row-major
        int c = i * 256 + tid;
        int m = c >> 3, ch = c & 7;
        cpa16(su + (m * ASTR + ch * 4) * 4, A + (size_t)(m0 + m) * K_ + kk + ch * 4);
    }
    #pragma unroll
    for (int i = 0; i < 4; i++) {               // B: 32k x 128n, row-major
        int c = i * 256 + tid;
        int k = c >> 5, ch = c & 31;
        cpa16(bu + (k * BSTR + ch * 4) * 4, W + (size_t)(kk + k) * N + n0 + ch * 4);
    }
}

template <int MODE>
__global__ __launch_bounds__(256, 2) void gemm_f16(
    const float* __restrict__ Ain, const float* __restrict__ W,
    const float* __restrict__ bias, float* __restrict__ out)
{
    const int N = MODE ? C_ : N3_;
    extern __shared__ float dsm[];
    const uint32_t sb = smem_u32(dsm);

    // device-side symbol (host-side g_y would be the host shadow address)
    const float* A = MODE ? (const float*)g_y : Ain;

    const int tid  = threadIdx.x;
    const int wid  = tid >> 5;
    const int lane = tid & 31;
    const int g  = lane >> 2;
    const int tq = lane & 3;
    const int wm = wid >> 2;
    const int wn = wid & 3;
    const int m0 = blockIdx.y * 128;
    const int n0 = blockIdx.x * 128;

    float acc[4][4][4] = {};

    gemm_load_stage(sb, A, W, m0, n0, 0, N, tid);
    CP_COMMIT();

    for (int kk = 0; kk < K_; kk += 32) {
        const int s = (kk >> 5) & 1;
        if (kk + 32 < K_)
            gemm_load_stage(sb + (uint32_t)(s ^ 1) * STG_W * 4, A, W, m0, n0,
                            kk + 32, N, tid);
        CP_COMMIT();
        CP_WAIT1();
        __syncthreads();

        const float* As = dsm + s * STG_W;
        const float* Bs = As + AS_W;

        #pragma unroll
        for (int ks = 0; ks < 2; ks++) {
            const int k0 = ks * 16;
            uint32_t ah[4][4], al[4][4], bh[4][2];
            #pragma unroll
            for (int mi = 0; mi < 4; mi++) {
                int mb = wm * 64 + mi * 16 + g;
                float2 p;
                p = *(const float2*)(As + (size_t)mb * ASTR + k0 + 2*tq);
                split2h(p.x, p.y, ah[mi][0], al[mi][0]);
                p = *(const float2*)(As + (size_t)(mb + 8) * ASTR + k0 + 2*tq);
                split2h(p.x, p.y, ah[mi][1], al[mi][1]);
                p = *(const float2*)(As + (size_t)mb * ASTR + k0 + 2*tq + 8);
                split2h(p.x, p.y, ah[mi][2], al[mi][2]);
                p = *(const float2*)(As + (size_t)(mb + 8) * ASTR + k0 + 2*tq + 8);
                split2h(p.x, p.y, ah[mi][3], al[mi][3]);
            }
            #pragma unroll
            for (int ni = 0; ni < 4; ni++) {
                int nb = wn * 32 + ni * 8 + g;
                bh[ni][0] = cvt2h(Bs[(size_t)(k0 + 2*tq)     * BSTR + nb],
                                  Bs[(size_t)(k0 + 2*tq + 1) * BSTR + nb]);
                bh[ni][1] = cvt2h(Bs[(size_t)(k0 + 2*tq + 8) * BSTR + nb],
                                  Bs[(size_t)(k0 + 2*tq + 9) * BSTR + nb]);
            }
            #pragma unroll
            for (int mi = 0; mi < 4; mi++)
                #pragma unroll
                for (int ni = 0; ni < 4; ni++) {
                    mma_f16(acc[mi][ni], ah[mi], bh[ni]);
                    mma_f16(acc[mi][ni], al[mi], bh[ni]);
                }
        }
        __syncthreads();
    }

    // ------------- epilogue -------------
    #pragma unroll
    for (int mi = 0; mi < 4; mi++) {
        #pragma unroll
        for (int ni = 0; ni < 4; ni++) {
            const float* c = acc[mi][ni];
            int r0 = m0 + wm * 64 + mi * 16 + g;
            int nc = n0 + wn * 32 + ni * 8 + 2 * tq;
            #pragma unroll
            for (int half = 0; half < 2; half++) {
                int m = r0 + half * 8;
                float e = c[half * 2 + 0];
                float o = c[half * 2 + 1];
                if (MODE == 0) {
                    int b = m >> 11, t = m & 2047;
                    int sec = nc >> 10, cc = nc & 1023;
                    int hd = cc >> 6, d = cc & 63;       // d even
                    size_t idx = ((size_t)((b << 4) + hd) * T_ + t) * 32 + (d >> 1);
                    if (sec == 2) {
                        g_vp[idx] = cvt2h(e, o);
                    } else {
                        float co = g_cos[t * 32 + (d >> 1)];
                        float si = g_sin[t * 32 + (d >> 1)];
                        float oe = e * co - o * si;
                        float oo = e * si + o * co;
                        if (sec == 0) {
                            uint32_t ph, pl;
                            split2h(oe * 0.125f, oo * 0.125f, ph, pl);
                            g_qp_h[idx] = ph; g_qp_l[idx] = pl;
                        } else {
                            g_kp[idx] = cvt2h(oe, oo);
                        }
                    }
                } else {
                    float2 bv = *(const float2*)(bias + nc);
                    *(float2*)(out + (size_t)m * C_ + nc) =
                        make_float2(e + bv.x, o + bv.y);
                }
            }
        }
    }
}

// ---------------- MMA flash attention (fp16 2-pass, single K/V arrays) ------
#define KPSTR 36
#define KPW   (64 * KPSTR)                 // 2304 words per array
#define VRSTR 36
#define VRW   (64 * VRSTR)                 // 2304
#define ASTG_W (KPW + VRW)                 // 4608 words per raw stage (K + Vraw)
#define VP_BASE (2 * ASTG_W)               // 9216
#define VPSTG_W KPW                        // 2304 per Vp stage
#define ATTN_WORDS (VP_BASE + 2 * VPSTG_W) // 13824
#define ATTN_SMEM_B (ATTN_WORDS * 4)       // 55,296 B

__device__ __forceinline__ void attn_load_stage(
    uint32_t su, const uint32_t* __restrict__ kp,
    const uint32_t* __restrict__ vp, int kv0, int tid)
{
    #pragma unroll
    for (int i = 0; i < 2; i++) {    // K: 64 rows x 32 words, packed d-pairs
        int c = i * 256 + tid;
        int r = c >> 3, ch = (c & 7) * 4;
        cpa16(su + (r * KPSTR + ch) * 4, kp + (size_t)(kv0 + r) * 32 + ch);
    }
    #pragma unroll
    for (int i = 0; i < 2; i++) {    // V raw (packed along d)
        int c = i * 256 + tid;
        int r = c >> 3, ch = (c & 7) * 4;
        cpa16(su + (KPW + r * VRSTR + ch) * 4, vp + (size_t)(kv0 + r) * 32 + ch);
    }
}

__global__ __launch_bounds__(256, 2) void attn_mma() {
    extern __shared__ uint32_t sw[];
    const uint32_t sb = smem_u32(sw);
    const int tid  = threadIdx.x;
    const int wid  = tid >> 5, lane = tid & 31;
    const int g    = lane >> 2, tq = lane & 3;
    const int qt   = (int)gridDim.x - 1 - (int)blockIdx.x;  // heavy-first
    const int bh   = blockIdx.y;
    const int q0   = qt * 128;

    const uint32_t* kp = g_kp + (size_t)bh * T_ * 32;
    const uint32_t* vp = g_vp + (size_t)bh * T_ * 32;

    // ---- Q fragments straight from packed gmem ----
    const int wrow0 = q0 + wid * 16;
    uint32_t qh[4][4], ql[4][4];
    {
        const size_t r0 = ((size_t)bh * T_ + wrow0 + g) * 32;
        const size_t r8 = r0 + 8 * 32;
        #pragma unroll
        for (int ks = 0; ks < 4; ks++) {
            int cp0 = 8 * ks + tq;
            qh[ks][0] = g_qp_h[r0 + cp0];     ql[ks][0] = g_qp_l[r0 + cp0];
            qh[ks][1] = g_qp_h[r8 + cp0];     ql[ks][1] = g_qp_l[r8 + cp0];
            qh[ks][2] = g_qp_h[r0 + cp0 + 4]; ql[ks][2] = g_qp_l[r0 + cp0 + 4];
            qh[ks][3] = g_qp_h[r8 + cp0 + 4]; ql[ks][3] = g_qp_l[r8 + cp0 + 4];
        }
    }

    float accO[8][4] = {};
    float mrow[2] = {-1e30f, -1e30f};
    float lrow[2] = {0.0f, 0.0f};
    const int nkv = 2 * qt + 2;
    const int xorv = (g >> 1) & 3;

    attn_load_stage(sb, kp, vp, 0, tid);  CP_COMMIT();
    if (nkv > 1) attn_load_stage(sb + ASTG_W * 4, kp, vp, 64, tid);
    CP_COMMIT();

    for (int j = 0; j < nkv; j++) {
        const int s = j & 1;
        const int kv0 = j * 64;
        const uint32_t* Kh = sw + s * ASTG_W;
        const uint32_t* Vr = Kh + KPW;
        uint32_t* Vp = sw + VP_BASE + s * VPSTG_W;

        CP_WAIT1();
        __syncthreads();

        // ---- cooperative V repack: Vp[d][kvp ^ (dw&3)] via PRMT ----
        {
            const int dw = (lane >> 3) + 4 * wid;       // 0..31
            #pragma unroll
            for (int i = 0; i < 4; i++) {
                int kvp = (lane & 7) + 8 * i;
                int c = kvp ^ (dw & 3);
                uint32_t w0 = Vr[(2 * kvp) * VRSTR + dw];
                uint32_t w1 = Vr[(2 * kvp + 1) * VRSTR + dw];
                Vp[(2 * dw) * KPSTR + c]     = prmt(w0, w1, 0x5410);
                Vp[(2 * dw + 1) * KPSTR + c] = prmt(w0, w1, 0x7632);
            }
        }
        __syncthreads();

        if (kv0 <= wrow0 + 15) {
            // ---- S = Q @ K^T (2-pass: qh*K + ql*K) ----
            float accS[8][4] = {};
            #pragma unroll
            for (int ks = 0; ks < 4; ks++) {
                const int cp = 8 * ks + tq;
                #pragma unroll
                for (int nf = 0; nf < 8; nf++) {
                    const int nb = nf * 8 + g;
                    uint32_t kh[2];
                    kh[0] = Kh[nb * KPSTR + cp];
                    kh[1] = Kh[nb * KPSTR + cp + 4];
                    mma_f16(accS[nf], qh[ks], kh);
                    mma_f16(accS[nf], ql[ks], kh);
                }
            }

            // ---- causal mask ----
            if (kv0 + 63 > wrow0) {
                #pragma unroll
                for (int nf = 0; nf < 8; nf++)
                    #pragma unroll
                    for (int r = 0; r < 4; r++) {
                        int row = wrow0 + g + (r >> 1) * 8;
                        int col = kv0 + nf * 8 + 2 * tq + (r & 1);
                        if (col > row) accS[nf][r] = -1e30f;
                    }
            }

            // ---- online softmax (fexp2, no MUFU) ----
            #pragma unroll
            for (int hh = 0; hh < 2; hh++) {
                float mx = -1e30f;
                #pragma unroll
                for (int nf = 0; nf < 8; nf++)
                    mx = fmaxf(mx, fmaxf(accS[nf][2*hh], accS[nf][2*hh+1]));
                mx = fmaxf(mx, __shfl_xor_sync(0xffffffffu, mx, 1));
                mx = fmaxf(mx, __shfl_xor_sync(0xffffffffu, mx, 2));
                float mn = fmaxf(mrow[hh], mx);
                float corr = fexp2((mrow[hh] - mn) * L2E_);
                mrow[hh] = mn;
                float mnL = mn * L2E_;
                float ps = 0.0f;
                #pragma unroll
                for (int nf = 0; nf < 8; nf++) {
                    float p0 = fexp2(fmaf(accS[nf][2*hh],   L2E_, -mnL));
                    float p1 = fexp2(fmaf(accS[nf][2*hh+1], L2E_, -mnL));
                    accS[nf][2*hh] = p0; accS[nf][2*hh+1] = p1;
                    ps += p0 + p1;
                }
                ps += __shfl_xor_sync(0xffffffffu, ps, 1);
                ps += __shfl_xor_sync(0xffffffffu, ps, 2);
                lrow[hh] = lrow[hh] * corr + ps;
                #pragma unroll
                for (int nf = 0; nf < 8; nf++) {
                    accO[nf][2*hh]   *= corr;
                    accO[nf][2*hh+1] *= corr;
                }
            }

            // ---- O += P @ V (2-pass: ph*V + pl*V; P frags from accS regs) ----
            #pragma unroll
            for (int ks = 0; ks < 4; ks++) {
                uint32_t ph[4], pl[4];
                split2h(accS[2*ks][0],   accS[2*ks][1],   ph[0], pl[0]);
                split2h(accS[2*ks][2],   accS[2*ks][3],   ph[1], pl[1]);
                split2h(accS[2*ks+1][0], accS[2*ks+1][1], ph[2], pl[2]);
                split2h(accS[2*ks+1][2], accS[2*ks+1][3], ph[3], pl[3]);
                const int c0 = (8 * ks + tq) ^ xorv;
                const int c1 = (8 * ks + tq + 4) ^ xorv;
                #pragma unroll
                for (int nf = 0; nf < 8; nf++) {
                    const int nb = nf * 8 + g;
                    uint32_t vh[2];
                    vh[0] = Vp[nb * KPSTR + c0];
                    vh[1] = Vp[nb * KPSTR + c1];
                    mma_f16(accO[nf], ph, vh);
                    mma_f16(accO[nf], pl, vh);
                }
            }
        }
        __syncthreads();   // all reads of raw stage s done before refill

        if (j + 2 < nkv)
            attn_load_stage(sb + (uint32_t)s * ASTG_W * 4, kp, vp, kv0 + 128, tid);
        CP_COMMIT();
    }

    // ---- write y [B,T,C] raw fp32 (proj splits at frag load) ----
    const int b = bh >> 4, hd = bh & 15;
    #pragma unroll
    for (int hh = 0; hh < 2; hh++) {
        float inv = 1.0f / lrow[hh];
        int t = q0 + wid * 16 + g + hh * 8;
        float* yrow = g_y + (size_t)(b * T_ + t) * C_ + hd * 64;
        #pragma unroll
        for (int nf = 0; nf < 8; nf++)
            *(float2*)(yrow + nf * 8 + 2 * tq) =
                make_float2(accO[nf][2*hh] * inv, accO[nf][2*hh+1] * inv);
    }
}

// ---------------------------------------------------------------------------
extern "C" void kernel_launch(void* const* d_in, const int* in_sizes, int n_in,
                              void* d_out, int out_size)
{
    const float* x      = (const float*)d_in[0];
    const float* w_qkv  = (const float*)d_in[1];
    const float* w_proj = (const float*)d_in[2];
    const float* b_proj = (const float*)d_in[3];
    float* out = (float*)d_out;
    (void)in_sizes; (void)n_in; (void)out_size;

    cudaFuncSetAttribute(gemm_f16<0>,
                         cudaFuncAttributeMaxDynamicSharedMemorySize, GEMM_SMEM_BYTES);
    cudaFuncSetAttribute(gemm_f16<1>,
                         cudaFuncAttributeMaxDynamicSharedMemorySize, GEMM_SMEM_BYTES);
    cudaFuncSetAttribute(attn_mma,
                         cudaFuncAttributeMaxDynamicSharedMemorySize, ATTN_SMEM_B);

    rope_table_kernel<<<256, 256>>>();
    gemm_f16<0><<<dim3(N3_ / 128, M_ / 128), 256, GEMM_SMEM_BYTES>>>(x, w_qkv, nullptr, nullptr);
    attn_mma<<<dim3(T_ / 128, BH_), 256, ATTN_SMEM_B>>>();
    gemm_f16<1><<<dim3(C_ / 128, M_ / 128), 256, GEMM_SMEM_BYTES>>>(nullptr, w_proj, b_proj, out);
}

// round 13
// speedup vs baseline: 1.4908x; 1.0587x over previous
#include <cuda_runtime.h>
#include <cuda_fp16.h>
#include <math.h>
#include <stdint.h>

#define B_  2
#define T_  2048
#define C_  1024
#define H_  16
#define D_  64
#define BH_ 32
#define M_  4096
#define N3_ 3072
#define K_  1024
#define KP2_ 512      // packed k-pair words per row (K/2)

// ---------------- scratch (__device__ globals; no allocs allowed) -----------
__device__ uint32_t g_xp_h[M_*KP2_], g_xp_l[M_*KP2_];   // x packed hi/lo [m][kp]
__device__ uint32_t g_yp_h[M_*KP2_], g_yp_l[M_*KP2_];   // y packed hi/lo [m][kp]
__device__ uint32_t g_qp_h[BH_*T_*32], g_qp_l[BH_*T_*32];
__device__ uint32_t g_kp[BH_*T_*32];
__device__ uint32_t g_vp[BH_*T_*32];
__device__ float g_cos[T_*32], g_sin[T_*32];

// ---------------- helpers ----------------------------------------------------
__device__ __forceinline__ uint32_t smem_u32(const void* p) {
    uint32_t a;
    asm("{ .reg .u64 t; cvta.to.shared.u64 t, %1; cvt.u32.u64 %0, t; }"
        : "=r"(a) : "l"(p));
    return a;
}

// pack two fp32 into f16x2 (v0 -> low half)
__device__ __forceinline__ uint32_t cvt2h(float v0, float v1) {
    uint32_t r;
    asm("cvt.rn.f16x2.f32 %0, %1, %2;" : "=r"(r) : "f"(v1), "f"(v0));
    return r;
}

// split two fp32 into f16x2 hi-pair and f16x2 lo-pair (residuals)
__device__ __forceinline__ void split2h(float v0, float v1,
                                        uint32_t& h, uint32_t& l) {
    h = cvt2h(v0, v1);
    float h0, h1;
    asm("{ .reg .f16 lo, hi; mov.b32 {lo, hi}, %2;"
        "  cvt.f32.f16 %0, lo; cvt.f32.f16 %1, hi; }"
        : "=f"(h0), "=f"(h1) : "r"(h));
    l = cvt2h(v0 - h0, v1 - h1);
}

__device__ __forceinline__ uint32_t prmt(uint32_t a, uint32_t b, uint32_t sel) {
    uint32_t r;
    asm("prmt.b32 %0, %1, %2, %3;" : "=r"(r) : "r"(a), "r"(b), "r"(sel));
    return r;
}

__device__ __forceinline__ void mma_f16(float c[4], const uint32_t a[4],
                                        const uint32_t b[2]) {
    asm volatile(
        "mma.sync.aligned.m16n8k16.row.col.f32.f16.f16.f32 "
        "{%0,%1,%2,%3}, {%4,%5,%6,%7}, {%8,%9}, {%0,%1,%2,%3};"
        : "+f"(c[0]), "+f"(c[1]), "+f"(c[2]), "+f"(c[3])
        : "r"(a[0]), "r"(a[1]), "r"(a[2]), "r"(a[3]), "r"(b[0]), "r"(b[1]));
}

// fast exp2 on FMA/ALU pipes (no MUFU)
__device__ __forceinline__ float fexp2(float t) {
    t = fmaxf(t, -126.0f);
    float r = t + 12582912.0f;
    int   n = __float_as_int(r);
    float f = t - (r - 12582912.0f);
    float p = 1.33335581e-3f;
    p = fmaf(p, f, 9.61812911e-3f);
    p = fmaf(p, f, 5.55041087e-2f);
    p = fmaf(p, f, 2.40226507e-1f);
    p = fmaf(p, f, 6.93147180e-1f);
    p = fmaf(p, f, 1.0f);
    return __int_as_float(__float_as_int(p) + (n << 23));
}
#define L2E_ 1.4426950408889634f

__device__ __forceinline__ void cpa16(uint32_t s, const void* gp) {
    asm volatile("cp.async.cg.shared.global [%0], [%1], 16;" :: "r"(s), "l"(gp));
}
#define CP_COMMIT() asm volatile("cp.async.commit_group;" ::: "memory")
#define CP_WAIT1()  asm volatile("cp.async.wait_group 1;" ::: "memory")

// ---------------- RoPE table -------------------------------------------------
__global__ void rope_table_kernel() {
    int idx = blockIdx.x * 256 + threadIdx.x;   // 65536
    int t = idx >> 5, i = idx & 31;
    double inv = pow(10000.0, -(double)(2 * i) / 64.0);
    float ff = (float)t * (float)inv;
    double s, c;
    sincos((double)ff, &s, &c);
    g_cos[idx] = (float)c;
    g_sin[idx] = (float)s;
}

// ---------------- x -> packed fp16 hi/lo (off the hot path) -----------------
__global__ __launch_bounds__(256) void convert_x_kernel(const float* __restrict__ x) {
    int i = blockIdx.x * 256 + threadIdx.x;     // over M_*K_/4 float4s
    float4 v = ((const float4*)x)[i];
    uint2 h, l;
    split2h(v.x, v.y, h.x, l.x);
    split2h(v.z, v.w, h.y, l.y);
    ((uint2*)g_xp_h)[i] = h;
    ((uint2*)g_xp_l)[i] = l;
}

// ---------------- fp16 2-pass GEMM: packed A (zero-cvt), raw-fp32 B ---------
#define APSTR 20                      // packed A row stride (16 data + 4 pad)
#define AP_W (128 * APSTR)            // 2560 words per A array
#define BSTR 132                      // raw B row stride
#define BS_W (32 * BSTR)              // 4224 words
#define STG_W (2 * AP_W + BS_W)       // 9344 words / stage
#define GEMM_SMEM_BYTES (2 * STG_W * 4)  // 74,752 B

__device__ __forceinline__ void gemm_load_stage(
    uint32_t su, const uint32_t* __restrict__ Aph, const uint32_t* __restrict__ Apl,
    const float* __restrict__ W, int m0, int n0, int jc, int N, int tid)
{
    // A hi/lo: 128 rows x 16 pair-words = 512 quads each
    #pragma unroll
    for (int i = 0; i < 2; i++) {
        int q = i * 256 + tid;
        int row = q >> 2, ch = (q & 3) * 4;
        const size_t ga = (size_t)(m0 + row) * KP2_ + jc * 16 + ch;
        cpa16(su + (row * APSTR + ch) * 4,            Aph + ga);
        cpa16(su + (AP_W + row * APSTR + ch) * 4,     Apl + ga);
    }
    // B raw fp32: 32k x 128n
    const uint32_t bu = su + 2 * AP_W * 4;
    #pragma unroll
    for (int i = 0; i < 4; i++) {
        int c = i * 256 + tid;
        int k = c >> 5, ch = (c & 31) * 4;
        cpa16(bu + (k * BSTR + ch) * 4, W + (size_t)(jc * 32 + k) * N + n0 + ch);
    }
}

template <int MODE>
__global__ __launch_bounds__(256, 2) void gemm_f16(
    const float* __restrict__ W, const float* __restrict__ bias,
    float* __restrict__ out)
{
    const int N = MODE ? C_ : N3_;
    extern __shared__ uint32_t dsm[];
    const uint32_t sb = smem_u32(dsm);

    // device-side symbols (host-side would give host shadow addresses)
    const uint32_t* Aph = MODE ? g_yp_h : g_xp_h;
    const uint32_t* Apl = MODE ? g_yp_l : g_xp_l;

    const int tid  = threadIdx.x;
    const int wid  = tid >> 5;
    const int lane = tid & 31;
    const int g  = lane >> 2;
    const int tq = lane & 3;
    const int wm = wid >> 2;
    const int wn = wid & 3;
    const int m0 = blockIdx.y * 128;
    const int n0 = blockIdx.x * 128;

    float acc[4][4][4] = {};

    gemm_load_stage(sb, Aph, Apl, W, m0, n0, 0, N, tid);
    CP_COMMIT();

    for (int jc = 0; jc < K_ / 32; jc++) {
        const int s = jc & 1;
        if (jc + 1 < K_ / 32)
            gemm_load_stage(sb + (uint32_t)(s ^ 1) * STG_W * 4, Aph, Apl, W,
                            m0, n0, jc + 1, N, tid);
        CP_COMMIT();
        CP_WAIT1();
        __syncthreads();

        const uint32_t* Ah = dsm + s * STG_W;
        const uint32_t* Al = Ah + AP_W;
        const float*    Bs = (const float*)(Ah + 2 * AP_W);

        #pragma unroll
        for (int ks = 0; ks < 2; ks++) {
            const int cp = 8 * ks + tq;
            const int k0 = 16 * ks;
            uint32_t ah[4][4], al[4][4], bh[4][2];
            #pragma unroll
            for (int mi = 0; mi < 4; mi++) {
                int mb = wm * 64 + mi * 16 + g;
                ah[mi][0] = Ah[mb * APSTR + cp];
                ah[mi][1] = Ah[(mb + 8) * APSTR + cp];
                ah[mi][2] = Ah[mb * APSTR + cp + 4];
                ah[mi][3] = Ah[(mb + 8) * APSTR + cp + 4];
                al[mi][0] = Al[mb * APSTR + cp];
                al[mi][1] = Al[(mb + 8) * APSTR + cp];
                al[mi][2] = Al[mb * APSTR + cp + 4];
                al[mi][3] = Al[(mb + 8) * APSTR + cp + 4];
            }
            #pragma unroll
            for (int ni = 0; ni < 4; ni++) {
                int nb = wn * 32 + ni * 8 + g;
                bh[ni][0] = cvt2h(Bs[(size_t)(k0 + 2*tq)     * BSTR + nb],
                                  Bs[(size_t)(k0 + 2*tq + 1) * BSTR + nb]);
                bh[ni][1] = cvt2h(Bs[(size_t)(k0 + 2*tq + 8) * BSTR + nb],
                                  Bs[(size_t)(k0 + 2*tq + 9) * BSTR + nb]);
            }
            #pragma unroll
            for (int mi = 0; mi < 4; mi++)
                #pragma unroll
                for (int ni = 0; ni < 4; ni++) {
                    mma_f16(acc[mi][ni], ah[mi], bh[ni]);
                    mma_f16(acc[mi][ni], al[mi], bh[ni]);
                }
        }
        __syncthreads();
    }

    // ------------- epilogue -------------
    #pragma unroll
    for (int mi = 0; mi < 4; mi++) {
        #pragma unroll
        for (int ni = 0; ni < 4; ni++) {
            const float* c = acc[mi][ni];
            int r0 = m0 + wm * 64 + mi * 16 + g;
            int nc = n0 + wn * 32 + ni * 8 + 2 * tq;
            #pragma unroll
            for (int half = 0; half < 2; half++) {
                int m = r0 + half * 8;
                float e = c[half * 2 + 0];
                float o = c[half * 2 + 1];
                if (MODE == 0) {
                    int b = m >> 11, t = m & 2047;
                    int sec = nc >> 10, cc = nc & 1023;
                    int hd = cc >> 6, d = cc & 63;       // d even
                    size_t idx = ((size_t)((b << 4) + hd) * T_ + t) * 32 + (d >> 1);
                    if (sec == 2) {
                        g_vp[idx] = cvt2h(e, o);
                    } else {
                        float co = g_cos[t * 32 + (d >> 1)];
                        float si = g_sin[t * 32 + (d >> 1)];
                        float oe = e * co - o * si;
                        float oo = e * si + o * co;
                        if (sec == 0) {
                            uint32_t ph, pl;
                            split2h(oe * 0.125f, oo * 0.125f, ph, pl);
                            g_qp_h[idx] = ph; g_qp_l[idx] = pl;
                        } else {
                            g_kp[idx] = cvt2h(oe, oo);
                        }
                    }
                } else {
                    float2 bv = *(const float2*)(bias + nc);
                    *(float2*)(out + (size_t)m * C_ + nc) =
                        make_float2(e + bv.x, o + bv.y);
                }
            }
        }
    }
}

// ---------------- MMA flash attention (fp16 2-pass, single K/V arrays) ------
#define KPSTR 36
#define KPW   (64 * KPSTR)                 // 2304 words per array
#define VRSTR 36
#define VRW   (64 * VRSTR)                 // 2304
#define ASTG_W (KPW + VRW)                 // 4608 words per raw stage (K + Vraw)
#define VP_BASE (2 * ASTG_W)               // 9216
#define VPSTG_W KPW                        // 2304 per Vp stage
#define ATTN_WORDS (VP_BASE + 2 * VPSTG_W) // 13824
#define ATTN_SMEM_B (ATTN_WORDS * 4)       // 55,296 B

__device__ __forceinline__ void attn_load_stage(
    uint32_t su, const uint32_t* __restrict__ kp,
    const uint32_t* __restrict__ vp, int kv0, int tid)
{
    #pragma unroll
    for (int i = 0; i < 2; i++) {    // K: 64 rows x 32 words, packed d-pairs
        int c = i * 256 + tid;
        int r = c >> 3, ch = (c & 7) * 4;
        cpa16(su + (r * KPSTR + ch) * 4, kp + (size_t)(kv0 + r) * 32 + ch);
    }
    #pragma unroll
    for (int i = 0; i < 2; i++) {    // V raw (packed along d)
        int c = i * 256 + tid;
        int r = c >> 3, ch = (c & 7) * 4;
        cpa16(su + (KPW + r * VRSTR + ch) * 4, vp + (size_t)(kv0 + r) * 32 + ch);
    }
}

__global__ __launch_bounds__(256, 2) void attn_mma() {
    extern __shared__ uint32_t sw[];
    const uint32_t sb = smem_u32(sw);
    const int tid  = threadIdx.x;
    const int wid  = tid >> 5, lane = tid & 31;
    const int g    = lane >> 2, tq = lane & 3;
    const int qt   = (int)gridDim.x - 1 - (int)blockIdx.x;  // heavy-first
    const int bh   = blockIdx.y;
    const int q0   = qt * 128;

    const uint32_t* kp = g_kp + (size_t)bh * T_ * 32;
    const uint32_t* vp = g_vp + (size_t)bh * T_ * 32;

    // ---- Q fragments straight from packed gmem ----
    const int wrow0 = q0 + wid * 16;
    uint32_t qh[4][4], ql[4][4];
    {
        const size_t r0 = ((size_t)bh * T_ + wrow0 + g) * 32;
        const size_t r8 = r0 + 8 * 32;
        #pragma unroll
        for (int ks = 0; ks < 4; ks++) {
            int cp0 = 8 * ks + tq;
            qh[ks][0] = g_qp_h[r0 + cp0];     ql[ks][0] = g_qp_l[r0 + cp0];
            qh[ks][1] = g_qp_h[r8 + cp0];     ql[ks][1] = g_qp_l[r8 + cp0];
            qh[ks][2] = g_qp_h[r0 + cp0 + 4]; ql[ks][2] = g_qp_l[r0 + cp0 + 4];
            qh[ks][3] = g_qp_h[r8 + cp0 + 4]; ql[ks][3] = g_qp_l[r8 + cp0 + 4];
        }
    }

    float accO[8][4] = {};
    float mrow[2] = {-1e30f, -1e30f};
    float lrow[2] = {0.0f, 0.0f};
    const int nkv = 2 * qt + 2;
    const int xorv = (g >> 1) & 3;

    attn_load_stage(sb, kp, vp, 0, tid);  CP_COMMIT();
    if (nkv > 1) attn_load_stage(sb + ASTG_W * 4, kp, vp, 64, tid);
    CP_COMMIT();

    for (int j = 0; j < nkv; j++) {
        const int s = j & 1;
        const int kv0 = j * 64;
        const uint32_t* Kh = sw + s * ASTG_W;
        const uint32_t* Vr = Kh + KPW;
        uint32_t* Vp = sw + VP_BASE + s * VPSTG_W;

        CP_WAIT1();
        __syncthreads();

        // ---- cooperative V repack: Vp[d][kvp ^ (dw&3)] via PRMT ----
        {
            const int dw = (lane >> 3) + 4 * wid;       // 0..31
            #pragma unroll
            for (int i = 0; i < 4; i++) {
                int kvp = (lane & 7) + 8 * i;
                int c = kvp ^ (dw & 3);
                uint32_t w0 = Vr[(2 * kvp) * VRSTR + dw];
                uint32_t w1 = Vr[(2 * kvp + 1) * VRSTR + dw];
                Vp[(2 * dw) * KPSTR + c]     = prmt(w0, w1, 0x5410);
                Vp[(2 * dw + 1) * KPSTR + c] = prmt(w0, w1, 0x7632);
            }
        }
        __syncthreads();

        if (kv0 <= wrow0 + 15) {
            // ---- S = Q @ K^T (2-pass: qh*K + ql*K) ----
            float accS[8][4] = {};
            #pragma unroll
            for (int ks = 0; ks < 4; ks++) {
                const int cp = 8 * ks + tq;
                #pragma unroll
                for (int nf = 0; nf < 8; nf++) {
                    const int nb = nf * 8 + g;
                    uint32_t kh[2];
                    kh[0] = Kh[nb * KPSTR + cp];
                    kh[1] = Kh[nb * KPSTR + cp + 4];
                    mma_f16(accS[nf], qh[ks], kh);
                    mma_f16(accS[nf], ql[ks], kh);
                }
            }

            // ---- causal mask ----
            if (kv0 + 63 > wrow0) {
                #pragma unroll
                for (int nf = 0; nf < 8; nf++)
                    #pragma unroll
                    for (int r = 0; r < 4; r++) {
                        int row = wrow0 + g + (r >> 1) * 8;
                        int col = kv0 + nf * 8 + 2 * tq + (r & 1);
                        if (col > row) accS[nf][r] = -1e30f;
                    }
            }

            // ---- online softmax (fexp2, no MUFU) ----
            #pragma unroll
            for (int hh = 0; hh < 2; hh++) {
                float mx = -1e30f;
                #pragma unroll
                for (int nf = 0; nf < 8; nf++)
                    mx = fmaxf(mx, fmaxf(accS[nf][2*hh], accS[nf][2*hh+1]));
                mx = fmaxf(mx, __shfl_xor_sync(0xffffffffu, mx, 1));
                mx = fmaxf(mx, __shfl_xor_sync(0xffffffffu, mx, 2));
                float mn = fmaxf(mrow[hh], mx);
                float corr = fexp2((mrow[hh] - mn) * L2E_);
                mrow[hh] = mn;
                float mnL = mn * L2E_;
                float ps = 0.0f;
                #pragma unroll
                for (int nf = 0; nf < 8; nf++) {
                    float p0 = fexp2(fmaf(accS[nf][2*hh],   L2E_, -mnL));
                    float p1 = fexp2(fmaf(accS[nf][2*hh+1], L2E_, -mnL));
                    accS[nf][2*hh] = p0; accS[nf][2*hh+1] = p1;
                    ps += p0 + p1;
                }
                ps += __shfl_xor_sync(0xffffffffu, ps, 1);
                ps += __shfl_xor_sync(0xffffffffu, ps, 2);
                lrow[hh] = lrow[hh] * corr + ps;
                #pragma unroll
                for (int nf = 0; nf < 8; nf++) {
                    accO[nf][2*hh]   *= corr;
                    accO[nf][2*hh+1] *= corr;
                }
            }

            // ---- O += P @ V (2-pass: ph*V + pl*V; P frags from accS regs) ----
            #pragma unroll
            for (int ks = 0; ks < 4; ks++) {
                uint32_t ph[4], pl[4];
                split2h(accS[2*ks][0],   accS[2*ks][1],   ph[0], pl[0]);
                split2h(accS[2*ks][2],   accS[2*ks][3],   ph[1], pl[1]);
                split2h(accS[2*ks+1][0], accS[2*ks+1][1], ph[2], pl[2]);
                split2h(accS[2*ks+1][2], accS[2*ks+1][3], ph[3], pl[3]);
                const int c0 = (8 * ks + tq) ^ xorv;
                const int c1 = (8 * ks + tq + 4) ^ xorv;
                #pragma unroll
                for (int nf = 0; nf < 8; nf++) {
                    const int nb = nf * 8 + g;
                    uint32_t vh[2];
                    vh[0] = Vp[nb * KPSTR + c0];
                    vh[1] = Vp[nb * KPSTR + c1];
                    mma_f16(accO[nf], ph, vh);
                    mma_f16(accO[nf], pl, vh);
                }
            }
        }
        __syncthreads();   // all reads of raw stage s done before refill

        if (j + 2 < nkv)
            attn_load_stage(sb + (uint32_t)s * ASTG_W * 4, kp, vp, kv0 + 128, tid);
        CP_COMMIT();
    }

    // ---- write y packed hi/lo [m][kp] (proj A-operand, zero-cvt there) ----
    const int b = bh >> 4, hd = bh & 15;
    #pragma unroll
    for (int hh = 0; hh < 2; hh++) {
        float inv = 1.0f / lrow[hh];
        int t = q0 + wid * 16 + g + hh * 8;
        size_t rowbase = (size_t)(b * T_ + t) * KP2_ + hd * 32;
        #pragma unroll
        for (int nf = 0; nf < 8; nf++) {
            uint32_t ph, pl;
            split2h(accO[nf][2*hh] * inv, accO[nf][2*hh+1] * inv, ph, pl);
            g_yp_h[rowbase + nf * 4 + tq] = ph;
            g_yp_l[rowbase + nf * 4 + tq] = pl;
        }
    }
}

// ---------------------------------------------------------------------------
extern "C" void kernel_launch(void* const* d_in, const int* in_sizes, int n_in,
                              void* d_out, int out_size)
{
    const float* x      = (const float*)d_in[0];
    const float* w_qkv  = (const float*)d_in[1];
    const float* w_proj = (const float*)d_in[2];
    const float* b_proj = (const float*)d_in[3];
    float* out = (float*)d_out;
    (void)in_sizes; (void)n_in; (void)out_size;

    cudaFuncSetAttribute(gemm_f16<0>,
                         cudaFuncAttributeMaxDynamicSharedMemorySize, GEMM_SMEM_BYTES);
    cudaFuncSetAttribute(gemm_f16<1>,
                         cudaFuncAttributeMaxDynamicSharedMemorySize, GEMM_SMEM_BYTES);
    cudaFuncSetAttribute(attn_mma,
                         cudaFuncAttributeMaxDynamicSharedMemorySize, ATTN_SMEM_B);

    rope_table_kernel<<<256, 256>>>();
    convert_x_kernel<<<M_ * K_ / 4 / 256, 256>>>(x);
    gemm_f16<0><<<dim3(N3_ / 128, M_ / 128), 256, GEMM_SMEM_BYTES>>>(w_qkv, nullptr, nullptr);
    attn_mma<<<dim3(T_ / 128, BH_), 256, ATTN_SMEM_B>>>();
    gemm_f16<1><<<dim3(C_ / 128, M_ / 128), 256, GEMM_SMEM_BYTES>>>(w_proj, b_proj, out);
}

// round 14
// speedup vs baseline: 1.7328x; 1.1624x over previous
#include <cuda_runtime.h>
#include <cuda_fp16.h>
#include <math.h>
#include <stdint.h>

#define B_  2
#define T_  2048
#define C_  1024
#define H_  16
#define D_  64
#define BH_ 32
#define M_  4096
#define N3_ 3072
#define K_  1024
#define KP2_ 512      // packed k-pair words per row (K/2)

// ---------------- scratch (__device__ globals; no allocs allowed) -----------
__device__ uint32_t g_xp_h[M_*KP2_], g_xp_l[M_*KP2_];   // x packed hi/lo [m][kp]
__device__ uint32_t g_yp_h[M_*KP2_], g_yp_l[M_*KP2_];   // y packed hi/lo [m][kp]
__device__ uint32_t g_wq16[KP2_*N3_];                   // w_qkv packed [kp][n]
__device__ uint32_t g_wp16[KP2_*C_];                    // w_proj packed [kp][n]
__device__ uint32_t g_qp_h[BH_*T_*32], g_qp_l[BH_*T_*32];
__device__ uint32_t g_kp[BH_*T_*32];
__device__ uint32_t g_vp[BH_*T_*32];
__device__ float g_cos[T_*32], g_sin[T_*32];

// ---------------- helpers ----------------------------------------------------
__device__ __forceinline__ uint32_t smem_u32(const void* p) {
    uint32_t a;
    asm("{ .reg .u64 t; cvta.to.shared.u64 t, %1; cvt.u32.u64 %0, t; }"
        : "=r"(a) : "l"(p));
    return a;
}

// pack two fp32 into f16x2 (v0 -> low half)
__device__ __forceinline__ uint32_t cvt2h(float v0, float v1) {
    uint32_t r;
    asm("cvt.rn.f16x2.f32 %0, %1, %2;" : "=r"(r) : "f"(v1), "f"(v0));
    return r;
}

// split two fp32 into f16x2 hi-pair and f16x2 lo-pair (residuals)
__device__ __forceinline__ void split2h(float v0, float v1,
                                        uint32_t& h, uint32_t& l) {
    h = cvt2h(v0, v1);
    float h0, h1;
    asm("{ .reg .f16 lo, hi; mov.b32 {lo, hi}, %2;"
        "  cvt.f32.f16 %0, lo; cvt.f32.f16 %1, hi; }"
        : "=f"(h0), "=f"(h1) : "r"(h));
    l = cvt2h(v0 - h0, v1 - h1);
}

__device__ __forceinline__ uint32_t prmt(uint32_t a, uint32_t b, uint32_t sel) {
    uint32_t r;
    asm("prmt.b32 %0, %1, %2, %3;" : "=r"(r) : "r"(a), "r"(b), "r"(sel));
    return r;
}

__device__ __forceinline__ void mma_f16(float c[4], const uint32_t a[4],
                                        const uint32_t b[2]) {
    asm volatile(
        "mma.sync.aligned.m16n8k16.row.col.f32.f16.f16.f32 "
        "{%0,%1,%2,%3}, {%4,%5,%6,%7}, {%8,%9}, {%0,%1,%2,%3};"
        : "+f"(c[0]), "+f"(c[1]), "+f"(c[2]), "+f"(c[3])
        : "r"(a[0]), "r"(a[1]), "r"(a[2]), "r"(a[3]), "r"(b[0]), "r"(b[1]));
}

// fast exp2 on FMA/ALU pipes (no MUFU)
__device__ __forceinline__ float fexp2(float t) {
    t = fmaxf(t, -126.0f);
    float r = t + 12582912.0f;
    int   n = __float_as_int(r);
    float f = t - (r - 12582912.0f);
    float p = 1.33335581e-3f;
    p = fmaf(p, f, 9.61812911e-3f);
    p = fmaf(p, f, 5.55041087e-2f);
    p = fmaf(p, f, 2.40226507e-1f);
    p = fmaf(p, f, 6.93147180e-1f);
    p = fmaf(p, f, 1.0f);
    return __int_as_float(__float_as_int(p) + (n << 23));
}
#define L2E_ 1.4426950408889634f

__device__ __forceinline__ void cpa16(uint32_t s, const void* gp) {
    asm volatile("cp.async.cg.shared.global [%0], [%1], 16;" :: "r"(s), "l"(gp));
}
#define CP_COMMIT() asm volatile("cp.async.commit_group;" ::: "memory")
#define CP_WAIT1()  asm volatile("cp.async.wait_group 1;" ::: "memory")

// ---------------- RoPE table -------------------------------------------------
__global__ void rope_table_kernel() {
    int idx = blockIdx.x * 256 + threadIdx.x;   // 65536
    int t = idx >> 5, i = idx & 31;
    double inv = pow(10000.0, -(double)(2 * i) / 64.0);
    float ff = (float)t * (float)inv;
    double s, c;
    sincos((double)ff, &s, &c);
    g_cos[idx] = (float)c;
    g_sin[idx] = (float)s;
}

// ---------------- converters (off the hot path) ------------------------------
__global__ __launch_bounds__(256) void convert_x_kernel(const float* __restrict__ x) {
    int i = blockIdx.x * 256 + threadIdx.x;     // over M_*K_/4 float4s
    float4 v = ((const float4*)x)[i];
    uint2 h, l;
    split2h(v.x, v.y, h.x, l.x);
    split2h(v.z, v.w, h.y, l.y);
    ((uint2*)g_xp_h)[i] = h;
    ((uint2*)g_xp_l)[i] = l;
}

// W[K][N] fp32 -> packed fp16 [kp][n] (pair k,k+1 per word; no transpose)
template <int WHICH>
__global__ __launch_bounds__(256) void convert_w_kernel(
    const float* __restrict__ W, int N)
{
    uint32_t* __restrict__ dst = WHICH ? g_wp16 : g_wq16;   // device-side symbol!
    int i = blockIdx.x * 256 + threadIdx.x;     // over (K_/2)*N/4 quads
    int kp  = i / (N >> 2);
    int nc4 = (i - kp * (N >> 2)) << 2;
    float4 a = *(const float4*)(W + (size_t)(2 * kp)     * N + nc4);
    float4 b = *(const float4*)(W + (size_t)(2 * kp + 1) * N + nc4);
    uint4 o;
    o.x = cvt2h(a.x, b.x);
    o.y = cvt2h(a.y, b.y);
    o.z = cvt2h(a.z, b.z);
    o.w = cvt2h(a.w, b.w);
    ((uint4*)dst)[i] = o;
}

// ---------------- fp16 2-pass GEMM: packed A + packed B (zero-cvt loop) -----
#define APSTR 20                      // packed A row stride (16 data + 4 pad)
#define AP_W (128 * APSTR)            // 2560 words per A array
#define BPSTR 136                     // packed B row stride (frag banks 8tq+g)
#define BP_W (16 * BPSTR)             // 2176 words
#define STG_W (2 * AP_W + BP_W)       // 7296 words / stage
#define GEMM_SMEM_BYTES (2 * STG_W * 4)  // 58,368 B

__device__ __forceinline__ void gemm_load_stage(
    uint32_t su, const uint32_t* __restrict__ Aph, const uint32_t* __restrict__ Apl,
    const uint32_t* __restrict__ Wp, int m0, int n0, int jc, int N, int tid)
{
    // A hi/lo: 128 rows x 16 pair-words = 512 quads each
    #pragma unroll
    for (int i = 0; i < 2; i++) {
        int q = i * 256 + tid;
        int row = q >> 2, ch = (q & 3) * 4;
        const size_t ga = (size_t)(m0 + row) * KP2_ + jc * 16 + ch;
        cpa16(su + (row * APSTR + ch) * 4,            Aph + ga);
        cpa16(su + (AP_W + row * APSTR + ch) * 4,     Apl + ga);
    }
    // B packed: 16 kp rows x 128 n words = 512 quads
    const uint32_t bu = su + 2 * AP_W * 4;
    #pragma unroll
    for (int i = 0; i < 2; i++) {
        int q = i * 256 + tid;
        int row = q >> 5, ch = (q & 31) * 4;
        cpa16(bu + (row * BPSTR + ch) * 4,
              Wp + (size_t)(jc * 16 + row) * N + n0 + ch);
    }
}

template <int MODE>
__global__ __launch_bounds__(256, 2) void gemm_f16(
    const float* __restrict__ bias, float* __restrict__ out)
{
    const int N = MODE ? C_ : N3_;
    extern __shared__ uint32_t dsm[];
    const uint32_t sb = smem_u32(dsm);

    // device-side symbols (host-side would give host shadow addresses)
    const uint32_t* Aph = MODE ? g_yp_h : g_xp_h;
    const uint32_t* Apl = MODE ? g_yp_l : g_xp_l;
    const uint32_t* Wp  = MODE ? g_wp16 : g_wq16;

    const int tid  = threadIdx.x;
    const int wid  = tid >> 5;
    const int lane = tid & 31;
    const int g  = lane >> 2;
    const int tq = lane & 3;
    const int wm = wid >> 2;
    const int wn = wid & 3;
    const int m0 = blockIdx.y * 128;
    const int n0 = blockIdx.x * 128;

    float acc[4][4][4] = {};

    gemm_load_stage(sb, Aph, Apl, Wp, m0, n0, 0, N, tid);
    CP_COMMIT();

    for (int jc = 0; jc < K_ / 32; jc++) {
        const int s = jc & 1;
        if (jc + 1 < K_ / 32)
            gemm_load_stage(sb + (uint32_t)(s ^ 1) * STG_W * 4, Aph, Apl, Wp,
                            m0, n0, jc + 1, N, tid);
        CP_COMMIT();
        CP_WAIT1();
        __syncthreads();

        const uint32_t* Ah = dsm + s * STG_W;
        const uint32_t* Al = Ah + AP_W;
        const uint32_t* Bp = Ah + 2 * AP_W;

        #pragma unroll
        for (int ks = 0; ks < 2; ks++) {
            const int cp = 8 * ks + tq;
            uint32_t ah[4][4], al[4][4], bh[4][2];
            #pragma unroll
            for (int mi = 0; mi < 4; mi++) {
                int mb = wm * 64 + mi * 16 + g;
                ah[mi][0] = Ah[mb * APSTR + cp];
                ah[mi][1] = Ah[(mb + 8) * APSTR + cp];
                ah[mi][2] = Ah[mb * APSTR + cp + 4];
                ah[mi][3] = Ah[(mb + 8) * APSTR + cp + 4];
                al[mi][0] = Al[mb * APSTR + cp];
                al[mi][1] = Al[(mb + 8) * APSTR + cp];
                al[mi][2] = Al[mb * APSTR + cp + 4];
                al[mi][3] = Al[(mb + 8) * APSTR + cp + 4];
            }
            #pragma unroll
            for (int ni = 0; ni < 4; ni++) {
                int nb = wn * 32 + ni * 8 + g;
                bh[ni][0] = Bp[cp * BPSTR + nb];
                bh[ni][1] = Bp[(cp + 4) * BPSTR + nb];
            }
            #pragma unroll
            for (int mi = 0; mi < 4; mi++)
                #pragma unroll
                for (int ni = 0; ni < 4; ni++) {
                    mma_f16(acc[mi][ni], ah[mi], bh[ni]);
                    mma_f16(acc[mi][ni], al[mi], bh[ni]);
                }
        }
        __syncthreads();
    }

    // ------------- epilogue -------------
    #pragma unroll
    for (int mi = 0; mi < 4; mi++) {
        #pragma unroll
        for (int ni = 0; ni < 4; ni++) {
            const float* c = acc[mi][ni];
            int r0 = m0 + wm * 64 + mi * 16 + g;
            int nc = n0 + wn * 32 + ni * 8 + 2 * tq;
            #pragma unroll
            for (int half = 0; half < 2; half++) {
                int m = r0 + half * 8;
                float e = c[half * 2 + 0];
                float o = c[half * 2 + 1];
                if (MODE == 0) {
                    int b = m >> 11, t = m & 2047;
                    int sec = nc >> 10, cc = nc & 1023;
                    int hd = cc >> 6, d = cc & 63;       // d even
                    size_t idx = ((size_t)((b << 4) + hd) * T_ + t) * 32 + (d >> 1);
                    if (sec == 2) {
                        g_vp[idx] = cvt2h(e, o);
                    } else {
                        float co = g_cos[t * 32 + (d >> 1)];
                        float si = g_sin[t * 32 + (d >> 1)];
                        float oe = e * co - o * si;
                        float oo = e * si + o * co;
                        if (sec == 0) {
                            uint32_t ph, pl;
                            split2h(oe * 0.125f, oo * 0.125f, ph, pl);
                            g_qp_h[idx] = ph; g_qp_l[idx] = pl;
                        } else {
                            g_kp[idx] = cvt2h(oe, oo);
                        }
                    }
                } else {
                    float2 bv = *(const float2*)(bias + nc);
                    *(float2*)(out + (size_t)m * C_ + nc) =
                        make_float2(e + bv.x, o + bv.y);
                }
            }
        }
    }
}

// ---------------- MMA flash attention (fp16; P single-pass) -----------------
#define KPSTR 36
#define KPW   (64 * KPSTR)                 // 2304 words per array
#define VRSTR 36
#define VRW   (64 * VRSTR)                 // 2304
#define ASTG_W (KPW + VRW)                 // 4608 words per raw stage (K + Vraw)
#define VP_BASE (2 * ASTG_W)               // 9216
#define VPSTG_W KPW                        // 2304 per Vp stage
#define ATTN_WORDS (VP_BASE + 2 * VPSTG_W) // 13824
#define ATTN_SMEM_B (ATTN_WORDS * 4)       // 55,296 B

__device__ __forceinline__ void attn_load_stage(
    uint32_t su, const uint32_t* __restrict__ kp,
    const uint32_t* __restrict__ vp, int kv0, int tid)
{
    #pragma unroll
    for (int i = 0; i < 2; i++) {    // K: 64 rows x 32 words, packed d-pairs
        int c = i * 256 + tid;
        int r = c >> 3, ch = (c & 7) * 4;
        cpa16(su + (r * KPSTR + ch) * 4, kp + (size_t)(kv0 + r) * 32 + ch);
    }
    #pragma unroll
    for (int i = 0; i < 2; i++) {    // V raw (packed along d)
        int c = i * 256 + tid;
        int r = c >> 3, ch = (c & 7) * 4;
        cpa16(su + (KPW + r * VRSTR + ch) * 4, vp + (size_t)(kv0 + r) * 32 + ch);
    }
}

__global__ __launch_bounds__(256, 2) void attn_mma() {
    extern __shared__ uint32_t sw[];
    const uint32_t sb = smem_u32(sw);
    const int tid  = threadIdx.x;
    const int wid  = tid >> 5, lane = tid & 31;
    const int g    = lane >> 2, tq = lane & 3;
    const int qt   = (int)gridDim.x - 1 - (int)blockIdx.x;  // heavy-first
    const int bh   = blockIdx.y;
    const int q0   = qt * 128;

    const uint32_t* kp = g_kp + (size_t)bh * T_ * 32;
    const uint32_t* vp = g_vp + (size_t)bh * T_ * 32;

    // ---- Q fragments straight from packed gmem ----
    const int wrow0 = q0 + wid * 16;
    uint32_t qh[4][4], ql[4][4];
    {
        const size_t r0 = ((size_t)bh * T_ + wrow0 + g) * 32;
        const size_t r8 = r0 + 8 * 32;
        #pragma unroll
        for (int ks = 0; ks < 4; ks++) {
            int cp0 = 8 * ks + tq;
            qh[ks][0] = g_qp_h[r0 + cp0];     ql[ks][0] = g_qp_l[r0 + cp0];
            qh[ks][1] = g_qp_h[r8 + cp0];     ql[ks][1] = g_qp_l[r8 + cp0];
            qh[ks][2] = g_qp_h[r0 + cp0 + 4]; ql[ks][2] = g_qp_l[r0 + cp0 + 4];
            qh[ks][3] = g_qp_h[r8 + cp0 + 4]; ql[ks][3] = g_qp_l[r8 + cp0 + 4];
        }
    }

    float accO[8][4] = {};
    float mrow[2] = {-1e30f, -1e30f};
    float lrow[2] = {0.0f, 0.0f};
    const int nkv = 2 * qt + 2;
    const int xorv = (g >> 1) & 3;

    attn_load_stage(sb, kp, vp, 0, tid);  CP_COMMIT();
    if (nkv > 1) attn_load_stage(sb + ASTG_W * 4, kp, vp, 64, tid);
    CP_COMMIT();

    for (int j = 0; j < nkv; j++) {
        const int s = j & 1;
        const int kv0 = j * 64;
        const uint32_t* Kh = sw + s * ASTG_W;
        const uint32_t* Vr = Kh + KPW;
        uint32_t* Vp = sw + VP_BASE + s * VPSTG_W;

        CP_WAIT1();
        __syncthreads();

        // ---- cooperative V repack: Vp[d][kvp ^ (dw&3)] via PRMT ----
        {
            const int dw = (lane >> 3) + 4 * wid;       // 0..31
            #pragma unroll
            for (int i = 0; i < 4; i++) {
                int kvp = (lane & 7) + 8 * i;
                int c = kvp ^ (dw & 3);
                uint32_t w0 = Vr[(2 * kvp) * VRSTR + dw];
                uint32_t w1 = Vr[(2 * kvp + 1) * VRSTR + dw];
                Vp[(2 * dw) * KPSTR + c]     = prmt(w0, w1, 0x5410);
                Vp[(2 * dw + 1) * KPSTR + c] = prmt(w0, w1, 0x7632);
            }
        }
        __syncthreads();

        if (kv0 <= wrow0 + 15) {
            // ---- S = Q @ K^T (2-pass: qh*K + ql*K) ----
            float accS[8][4] = {};
            #pragma unroll
            for (int ks = 0; ks < 4; ks++) {
                const int cp = 8 * ks + tq;
                #pragma unroll
                for (int nf = 0; nf < 8; nf++) {
                    const int nb = nf * 8 + g;
                    uint32_t kh[2];
                    kh[0] = Kh[nb * KPSTR + cp];
                    kh[1] = Kh[nb * KPSTR + cp + 4];
                    mma_f16(accS[nf], qh[ks], kh);
                    mma_f16(accS[nf], ql[ks], kh);
                }
            }

            // ---- causal mask ----
            if (kv0 + 63 > wrow0) {
                #pragma unroll
                for (int nf = 0; nf < 8; nf++)
                    #pragma unroll
                    for (int r = 0; r < 4; r++) {
                        int row = wrow0 + g + (r >> 1) * 8;
                        int col = kv0 + nf * 8 + 2 * tq + (r & 1);
                        if (col > row) accS[nf][r] = -1e30f;
                    }
            }

            // ---- online softmax (fexp2, no MUFU) ----
            #pragma unroll
            for (int hh = 0; hh < 2; hh++) {
                float mx = -1e30f;
                #pragma unroll
                for (int nf = 0; nf < 8; nf++)
                    mx = fmaxf(mx, fmaxf(accS[nf][2*hh], accS[nf][2*hh+1]));
                mx = fmaxf(mx, __shfl_xor_sync(0xffffffffu, mx, 1));
                mx = fmaxf(mx, __shfl_xor_sync(0xffffffffu, mx, 2));
                float mn = fmaxf(mrow[hh], mx);
                float corr = fexp2((mrow[hh] - mn) * L2E_);
                mrow[hh] = mn;
                float mnL = mn * L2E_;
                float ps = 0.0f;
                #pragma unroll
                for (int nf = 0; nf < 8; nf++) {
                    float p0 = fexp2(fmaf(accS[nf][2*hh],   L2E_, -mnL));
                    float p1 = fexp2(fmaf(accS[nf][2*hh+1], L2E_, -mnL));
                    accS[nf][2*hh] = p0; accS[nf][2*hh+1] = p1;
                    ps += p0 + p1;
                }
                ps += __shfl_xor_sync(0xffffffffu, ps, 1);
                ps += __shfl_xor_sync(0xffffffffu, ps, 2);
                lrow[hh] = lrow[hh] * corr + ps;
                #pragma unroll
                for (int nf = 0; nf < 8; nf++) {
                    accO[nf][2*hh]   *= corr;
                    accO[nf][2*hh+1] *= corr;
                }
            }

            // ---- O += P @ V (P single-pass fp16; frags from accS regs) ----
            #pragma unroll
            for (int ks = 0; ks < 4; ks++) {
                uint32_t ph[4];
                ph[0] = cvt2h(accS[2*ks][0],   accS[2*ks][1]);
                ph[1] = cvt2h(accS[2*ks][2],   accS[2*ks][3]);
                ph[2] = cvt2h(accS[2*ks+1][0], accS[2*ks+1][1]);
                ph[3] = cvt2h(accS[2*ks+1][2], accS[2*ks+1][3]);
                const int c0 = (8 * ks + tq) ^ xorv;
                const int c1 = (8 * ks + tq + 4) ^ xorv;
                #pragma unroll
                for (int nf = 0; nf < 8; nf++) {
                    const int nb = nf * 8 + g;
                    uint32_t vh[2];
                    vh[0] = Vp[nb * KPSTR + c0];
                    vh[1] = Vp[nb * KPSTR + c1];
                    mma_f16(accO[nf], ph, vh);
                }
            }
        }
        __syncthreads();   // all reads of raw stage s done before refill

        if (j + 2 < nkv)
            attn_load_stage(sb + (uint32_t)s * ASTG_W * 4, kp, vp, kv0 + 128, tid);
        CP_COMMIT();
    }

    // ---- write y packed hi/lo [m][kp] (proj A-operand, zero-cvt there) ----
    const int b = bh >> 4, hd = bh & 15;
    #pragma unroll
    for (int hh = 0; hh < 2; hh++) {
        float inv = 1.0f / lrow[hh];
        int t = q0 + wid * 16 + g + hh * 8;
        size_t rowbase = (size_t)(b * T_ + t) * KP2_ + hd * 32;
        #pragma unroll
        for (int nf = 0; nf < 8; nf++) {
            uint32_t ph, pl;
            split2h(accO[nf][2*hh] * inv, accO[nf][2*hh+1] * inv, ph, pl);
            g_yp_h[rowbase + nf * 4 + tq] = ph;
            g_yp_l[rowbase + nf * 4 + tq] = pl;
        }
    }
}

// ---------------------------------------------------------------------------
extern "C" void kernel_launch(void* const* d_in, const int* in_sizes, int n_in,
                              void* d_out, int out_size)
{
    const float* x      = (const float*)d_in[0];
    const float* w_qkv  = (const float*)d_in[1];
    const float* w_proj = (const float*)d_in[2];
    const float* b_proj = (const float*)d_in[3];
    float* out = (float*)d_out;
    (void)in_sizes; (void)n_in; (void)out_size;

    cudaFuncSetAttribute(gemm_f16<0>,
                         cudaFuncAttributeMaxDynamicSharedMemorySize, GEMM_SMEM_BYTES);
    cudaFuncSetAttribute(gemm_f16<1>,
                         cudaFuncAttributeMaxDynamicSharedMemorySize, GEMM_SMEM_BYTES);
    cudaFuncSetAttribute(attn_mma,
                         cudaFuncAttributeMaxDynamicSharedMemorySize, ATTN_SMEM_B);

    rope_table_kernel<<<256, 256>>>();
    convert_x_kernel<<<M_ * K_ / 4 / 256, 256>>>(x);
    convert_w_kernel<0><<<(KP2_ * N3_ / 4) / 256, 256>>>(w_qkv, N3_);
    convert_w_kernel<1><<<(KP2_ * C_  / 4) / 256, 256>>>(w_proj, C_);
    gemm_f16<0><<<dim3(N3_ / 128, M_ / 128), 256, GEMM_SMEM_BYTES>>>(nullptr, nullptr);
    attn_mma<<<dim3(T_ / 128, BH_), 256, ATTN_SMEM_B>>>();
    gemm_f16<1><<<dim3(C_ / 128, M_ / 128), 256, GEMM_SMEM_BYTES>>>(b_proj, out);
}

// round 15
// speedup vs baseline: 1.8284x; 1.0552x over previous
#include <cuda_runtime.h>
#include <cuda_fp16.h>
#include <math.h>
#include <stdint.h>

#define B_  2
#define T_  2048
#define C_  1024
#define H_  16
#define D_  64
#define BH_ 32
#define M_  4096
#define N3_ 3072
#define K_  1024
#define KP2_ 512      // packed k-pair words per row (K/2)

// ---------------- scratch (__device__ globals; no allocs allowed) -----------
__device__ uint32_t g_xp_h[M_*KP2_], g_xp_l[M_*KP2_];   // x packed hi/lo [m][kp]
__device__ uint32_t g_yp_h[M_*KP2_], g_yp_l[M_*KP2_];   // y packed hi/lo [m][kp]
__device__ uint32_t g_wq16[KP2_*N3_];                   // w_qkv packed [kp][n]
__device__ uint32_t g_wp16[KP2_*C_];                    // w_proj packed [kp][n]
__device__ uint32_t g_qp_h[BH_*T_*32], g_qp_l[BH_*T_*32];
__device__ uint32_t g_kp[BH_*T_*32];                    // K packed d-pairs [t][dp]
__device__ __half   g_vt[BH_*D_*T_];                    // V TRANSPOSED fp16 [d][t]
__device__ float g_cos[T_*32], g_sin[T_*32];

// ---------------- helpers ----------------------------------------------------
__device__ __forceinline__ uint32_t smem_u32(const void* p) {
    uint32_t a;
    asm("{ .reg .u64 t; cvta.to.shared.u64 t, %1; cvt.u32.u64 %0, t; }"
        : "=r"(a) : "l"(p));
    return a;
}

// pack two fp32 into f16x2 (v0 -> low half)
__device__ __forceinline__ uint32_t cvt2h(float v0, float v1) {
    uint32_t r;
    asm("cvt.rn.f16x2.f32 %0, %1, %2;" : "=r"(r) : "f"(v1), "f"(v0));
    return r;
}

// split two fp32 into f16x2 hi-pair and f16x2 lo-pair (residuals)
__device__ __forceinline__ void split2h(float v0, float v1,
                                        uint32_t& h, uint32_t& l) {
    h = cvt2h(v0, v1);
    float h0, h1;
    asm("{ .reg .f16 lo, hi; mov.b32 {lo, hi}, %2;"
        "  cvt.f32.f16 %0, lo; cvt.f32.f16 %1, hi; }"
        : "=f"(h0), "=f"(h1) : "r"(h));
    l = cvt2h(v0 - h0, v1 - h1);
}

__device__ __forceinline__ void mma_f16(float c[4], const uint32_t a[4],
                                        const uint32_t b[2]) {
    asm volatile(
        "mma.sync.aligned.m16n8k16.row.col.f32.f16.f16.f32 "
        "{%0,%1,%2,%3}, {%4,%5,%6,%7}, {%8,%9}, {%0,%1,%2,%3};"
        : "+f"(c[0]), "+f"(c[1]), "+f"(c[2]), "+f"(c[3])
        : "r"(a[0]), "r"(a[1]), "r"(a[2]), "r"(a[3]), "r"(b[0]), "r"(b[1]));
}

// fast exp2 on FMA/ALU pipes (no MUFU)
__device__ __forceinline__ float fexp2(float t) {
    t = fmaxf(t, -126.0f);
    float r = t + 12582912.0f;
    int   n = __float_as_int(r);
    float f = t - (r - 12582912.0f);
    float p = 1.33335581e-3f;
    p = fmaf(p, f, 9.61812911e-3f);
    p = fmaf(p, f, 5.55041087e-2f);
    p = fmaf(p, f, 2.40226507e-1f);
    p = fmaf(p, f, 6.93147180e-1f);
    p = fmaf(p, f, 1.0f);
    return __int_as_float(__float_as_int(p) + (n << 23));
}
#define L2E_ 1.4426950408889634f

__device__ __forceinline__ void cpa16(uint32_t s, const void* gp) {
    asm volatile("cp.async.cg.shared.global [%0], [%1], 16;" :: "r"(s), "l"(gp));
}
#define CP_COMMIT() asm volatile("cp.async.commit_group;" ::: "memory")
#define CP_WAIT1()  asm volatile("cp.async.wait_group 1;" ::: "memory")

// ---------------- RoPE table (shared fp64 pow table; fp64 sincos kept) ------
__global__ void rope_table_kernel() {
    __shared__ float sinv[32];
    const int tid = threadIdx.x;
    if (tid < 32)
        sinv[tid] = (float)pow(10000.0, -(double)(2 * tid) / 64.0);
    __syncthreads();
    int idx = blockIdx.x * 256 + tid;           // 65536
    int t = idx >> 5, i = idx & 31;
    float ff = (float)t * sinv[i];              // fp32 rounding matches ref
    double s, c;
    sincos((double)ff, &s, &c);                 // fast-math-immune reduction
    g_cos[idx] = (float)c;
    g_sin[idx] = (float)s;
}

// ---------------- converters (off the hot path) ------------------------------
__global__ __launch_bounds__(256) void convert_x_kernel(const float* __restrict__ x) {
    int i = blockIdx.x * 256 + threadIdx.x;     // over M_*K_/4 float4s
    float4 v = ((const float4*)x)[i];
    uint2 h, l;
    split2h(v.x, v.y, h.x, l.x);
    split2h(v.z, v.w, h.y, l.y);
    ((uint2*)g_xp_h)[i] = h;
    ((uint2*)g_xp_l)[i] = l;
}

// W[K][N] fp32 -> packed fp16 [kp][n] (pair k,k+1 per word; no transpose)
template <int WHICH>
__global__ __launch_bounds__(256) void convert_w_kernel(
    const float* __restrict__ W, int N)
{
    uint32_t* __restrict__ dst = WHICH ? g_wp16 : g_wq16;   // device-side symbol!
    int i = blockIdx.x * 256 + threadIdx.x;     // over (K_/2)*N/4 quads
    int kp  = i / (N >> 2);
    int nc4 = (i - kp * (N >> 2)) << 2;
    float4 a = *(const float4*)(W + (size_t)(2 * kp)     * N + nc4);
    float4 b = *(const float4*)(W + (size_t)(2 * kp + 1) * N + nc4);
    uint4 o;
    o.x = cvt2h(a.x, b.x);
    o.y = cvt2h(a.y, b.y);
    o.z = cvt2h(a.z, b.z);
    o.w = cvt2h(a.w, b.w);
    ((uint4*)dst)[i] = o;
}

// ---------------- fp16 2-pass GEMM: packed A + packed B (zero-cvt loop) -----
#define APSTR 20                      // packed A row stride (16 data + 4 pad)
#define AP_W (128 * APSTR)            // 2560 words per A array
#define BPSTR 136                     // packed B row stride (frag banks 8tq+g)
#define BP_W (16 * BPSTR)             // 2176 words
#define STG_W (2 * AP_W + BP_W)       // 7296 words / stage
#define GEMM_SMEM_BYTES (2 * STG_W * 4)  // 58,368 B

__device__ __forceinline__ void gemm_load_stage(
    uint32_t su, const uint32_t* __restrict__ Aph, const uint32_t* __restrict__ Apl,
    const uint32_t* __restrict__ Wp, int m0, int n0, int jc, int N, int tid)
{
    // A hi/lo: 128 rows x 16 pair-words = 512 quads each
    #pragma unroll
    for (int i = 0; i < 2; i++) {
        int q = i * 256 + tid;
        int row = q >> 2, ch = (q & 3) * 4;
        const size_t ga = (size_t)(m0 + row) * KP2_ + jc * 16 + ch;
        cpa16(su + (row * APSTR + ch) * 4,            Aph + ga);
        cpa16(su + (AP_W + row * APSTR + ch) * 4,     Apl + ga);
    }
    // B packed: 16 kp rows x 128 n words = 512 quads
    const uint32_t bu = su + 2 * AP_W * 4;
    #pragma unroll
    for (int i = 0; i < 2; i++) {
        int q = i * 256 + tid;
        int row = q >> 5, ch = (q & 31) * 4;
        cpa16(bu + (row * BPSTR + ch) * 4,
              Wp + (size_t)(jc * 16 + row) * N + n0 + ch);
    }
}

template <int MODE>
__global__ __launch_bounds__(256, 2) void gemm_f16(
    const float* __restrict__ bias, float* __restrict__ out)
{
    const int N = MODE ? C_ : N3_;
    extern __shared__ uint32_t dsm[];
    const uint32_t sb = smem_u32(dsm);

    // device-side symbols (host-side would give host shadow addresses)
    const uint32_t* Aph = MODE ? g_yp_h : g_xp_h;
    const uint32_t* Apl = MODE ? g_yp_l : g_xp_l;
    const uint32_t* Wp  = MODE ? g_wp16 : g_wq16;

    const int tid  = threadIdx.x;
    const int wid  = tid >> 5;
    const int lane = tid & 31;
    const int g  = lane >> 2;
    const int tq = lane & 3;
    const int wm = wid >> 2;
    const int wn = wid & 3;
    const int m0 = blockIdx.y * 128;
    const int n0 = blockIdx.x * 128;

    float acc[4][4][4] = {};

    gemm_load_stage(sb, Aph, Apl, Wp, m0, n0, 0, N, tid);
    CP_COMMIT();

    for (int jc = 0; jc < K_ / 32; jc++) {
        const int s = jc & 1;
        if (jc + 1 < K_ / 32)
            gemm_load_stage(sb + (uint32_t)(s ^ 1) * STG_W * 4, Aph, Apl, Wp,
                            m0, n0, jc + 1, N, tid);
        CP_COMMIT();
        CP_WAIT1();
        __syncthreads();

        const uint32_t* Ah = dsm + s * STG_W;
        const uint32_t* Al = Ah + AP_W;
        const uint32_t* Bp = Ah + 2 * AP_W;

        #pragma unroll
        for (int ks = 0; ks < 2; ks++) {
            const int cp = 8 * ks + tq;
            uint32_t ah[4][4], al[4][4], bh[4][2];
            #pragma unroll
            for (int mi = 0; mi < 4; mi++) {
                int mb = wm * 64 + mi * 16 + g;
                ah[mi][0] = Ah[mb * APSTR + cp];
                ah[mi][1] = Ah[(mb + 8) * APSTR + cp];
                ah[mi][2] = Ah[mb * APSTR + cp + 4];
                ah[mi][3] = Ah[(mb + 8) * APSTR + cp + 4];
                al[mi][0] = Al[mb * APSTR + cp];
                al[mi][1] = Al[(mb + 8) * APSTR + cp];
                al[mi][2] = Al[mb * APSTR + cp + 4];
                al[mi][3] = Al[(mb + 8) * APSTR + cp + 4];
            }
            #pragma unroll
            for (int ni = 0; ni < 4; ni++) {
                int nb = wn * 32 + ni * 8 + g;
                bh[ni][0] = Bp[cp * BPSTR + nb];
                bh[ni][1] = Bp[(cp + 4) * BPSTR + nb];
            }
            #pragma unroll
            for (int mi = 0; mi < 4; mi++)
                #pragma unroll
                for (int ni = 0; ni < 4; ni++) {
                    mma_f16(acc[mi][ni], ah[mi], bh[ni]);
                    mma_f16(acc[mi][ni], al[mi], bh[ni]);
                }
        }
        __syncthreads();
    }

    // ------------- epilogue -------------
    #pragma unroll
    for (int mi = 0; mi < 4; mi++) {
        #pragma unroll
        for (int ni = 0; ni < 4; ni++) {
            const float* c = acc[mi][ni];
            int r0 = m0 + wm * 64 + mi * 16 + g;
            int nc = n0 + wn * 32 + ni * 8 + 2 * tq;
            #pragma unroll
            for (int half = 0; half < 2; half++) {
                int m = r0 + half * 8;
                float e = c[half * 2 + 0];
                float o = c[half * 2 + 1];
                if (MODE == 0) {
                    int b = m >> 11, t = m & 2047;
                    int sec = nc >> 10, cc = nc & 1023;
                    int hd = cc >> 6, d = cc & 63;       // d even
                    if (sec == 2) {
                        // V transposed fp16 [bh][d][t]: rows d and d+1
                        size_t vb = ((size_t)((b << 4) + hd) * D_ + d) * T_ + t;
                        g_vt[vb]      = __float2half(e);
                        g_vt[vb + T_] = __float2half(o);
                    } else {
                        size_t idx = ((size_t)((b << 4) + hd) * T_ + t) * 32 + (d >> 1);
                        float co = g_cos[t * 32 + (d >> 1)];
                        float si = g_sin[t * 32 + (d >> 1)];
                        float oe = e * co - o * si;
                        float oo = e * si + o * co;
                        if (sec == 0) {
                            uint32_t ph, pl;
                            split2h(oe * 0.125f, oo * 0.125f, ph, pl);
                            g_qp_h[idx] = ph; g_qp_l[idx] = pl;
                        } else {
                            g_kp[idx] = cvt2h(oe, oo);
                        }
                    }
                } else {
                    float2 bv = *(const float2*)(bias + nc);
                    *(float2*)(out + (size_t)m * C_ + nc) =
                        make_float2(e + bv.x, o + bv.y);
                }
            }
        }
    }
}

// ---------------- MMA flash attention (fp16; V pre-transposed, no repack) ---
#define KPSTR 36
#define KPW   (64 * KPSTR)                 // 2304 words (K tile)
#define VSTR  36
#define VT_W  (64 * VSTR)                  // 2304 words (V tile, [d][kvpair])
#define ASTG_W (KPW + VT_W)                // 4608 words per stage
#define ATTN_WORDS (2 * ASTG_W)            // 9216
#define ATTN_SMEM_B (ATTN_WORDS * 4)       // 36,864 B

__device__ __forceinline__ void attn_load_stage(
    uint32_t su, const uint32_t* __restrict__ kp,
    const __half* __restrict__ vt, int kv0, int tid)
{
    #pragma unroll
    for (int i = 0; i < 2; i++) {    // K: 64 kv rows x 32 words (d-pairs)
        int c = i * 256 + tid;
        int r = c >> 3, ch = (c & 7) * 4;
        cpa16(su + (r * KPSTR + ch) * 4, kp + (size_t)(kv0 + r) * 32 + ch);
    }
    #pragma unroll
    for (int i = 0; i < 2; i++) {    // V^T: 64 d rows x 64 halves (32 words)
        int c = i * 256 + tid;
        int r = c >> 3, ch = c & 7;
        cpa16(su + (KPW + r * VSTR + ch * 4) * 4,
              vt + (size_t)r * T_ + kv0 + ch * 8);
    }
}

__global__ __launch_bounds__(256, 2) void attn_mma() {
    extern __shared__ uint32_t sw[];
    const uint32_t sb = smem_u32(sw);
    const int tid  = threadIdx.x;
    const int wid  = tid >> 5, lane = tid & 31;
    const int g    = lane >> 2, tq = lane & 3;
    const int qt   = (int)gridDim.x - 1 - (int)blockIdx.x;  // heavy-first
    const int bh   = blockIdx.y;
    const int q0   = qt * 128;

    const uint32_t* kp = g_kp + (size_t)bh * T_ * 32;
    const __half*   vt = g_vt + (size_t)bh * D_ * T_;

    // ---- Q fragments straight from packed gmem ----
    const int wrow0 = q0 + wid * 16;
    uint32_t qh[4][4], ql[4][4];
    {
        const size_t r0 = ((size_t)bh * T_ + wrow0 + g) * 32;
        const size_t r8 = r0 + 8 * 32;
        #pragma unroll
        for (int ks = 0; ks < 4; ks++) {
            int cp0 = 8 * ks + tq;
            qh[ks][0] = g_qp_h[r0 + cp0];     ql[ks][0] = g_qp_l[r0 + cp0];
            qh[ks][1] = g_qp_h[r8 + cp0];     ql[ks][1] = g_qp_l[r8 + cp0];
            qh[ks][2] = g_qp_h[r0 + cp0 + 4]; ql[ks][2] = g_qp_l[r0 + cp0 + 4];
            qh[ks][3] = g_qp_h[r8 + cp0 + 4]; ql[ks][3] = g_qp_l[r8 + cp0 + 4];
        }
    }

    float accO[8][4] = {};
    float mrow[2] = {-1e30f, -1e30f};
    float lrow[2] = {0.0f, 0.0f};
    const int nkv = 2 * qt + 2;

    attn_load_stage(sb, kp, vt, 0, tid);  CP_COMMIT();
    if (nkv > 1) attn_load_stage(sb + ASTG_W * 4, kp, vt, 64, tid);
    CP_COMMIT();

    for (int j = 0; j < nkv; j++) {
        const int s = j & 1;
        const int kv0 = j * 64;
        const uint32_t* Kh = sw + s * ASTG_W;
        const uint32_t* Vs = Kh + KPW;

        CP_WAIT1();
        __syncthreads();

        if (kv0 <= wrow0 + 15) {
            // ---- S = Q @ K^T (2-pass: qh*K + ql*K) ----
            float accS[8][4] = {};
            #pragma unroll
            for (int ks = 0; ks < 4; ks++) {
                const int cp = 8 * ks + tq;
                #pragma unroll
                for (int nf = 0; nf < 8; nf++) {
                    const int nb = nf * 8 + g;
                    uint32_t kh[2];
                    kh[0] = Kh[nb * KPSTR + cp];
                    kh[1] = Kh[nb * KPSTR + cp + 4];
                    mma_f16(accS[nf], qh[ks], kh);
                    mma_f16(accS[nf], ql[ks], kh);
                }
            }

            // ---- causal mask ----
            if (kv0 + 63 > wrow0) {
                #pragma unroll
                for (int nf = 0; nf < 8; nf++)
                    #pragma unroll
                    for (int r = 0; r < 4; r++) {
                        int row = wrow0 + g + (r >> 1) * 8;
                        int col = kv0 + nf * 8 + 2 * tq + (r & 1);
                        if (col > row) accS[nf][r] = -1e30f;
                    }
            }

            // ---- online softmax (fexp2, no MUFU) ----
            #pragma unroll
            for (int hh = 0; hh < 2; hh++) {
                float mx = -1e30f;
                #pragma unroll
                for (int nf = 0; nf < 8; nf++)
                    mx = fmaxf(mx, fmaxf(accS[nf][2*hh], accS[nf][2*hh+1]));
                mx = fmaxf(mx, __shfl_xor_sync(0xffffffffu, mx, 1));
                mx = fmaxf(mx, __shfl_xor_sync(0xffffffffu, mx, 2));
                float mn = fmaxf(mrow[hh], mx);
                float corr = fexp2((mrow[hh] - mn) * L2E_);
                mrow[hh] = mn;
                float mnL = mn * L2E_;
                float ps = 0.0f;
                #pragma unroll
                for (int nf = 0; nf < 8; nf++) {
                    float p0 = fexp2(fmaf(accS[nf][2*hh],   L2E_, -mnL));
                    float p1 = fexp2(fmaf(accS[nf][2*hh+1], L2E_, -mnL));
                    accS[nf][2*hh] = p0; accS[nf][2*hh+1] = p1;
                    ps += p0 + p1;
                }
                ps += __shfl_xor_sync(0xffffffffu, ps, 1);
                ps += __shfl_xor_sync(0xffffffffu, ps, 2);
                lrow[hh] = lrow[hh] * corr + ps;
                #pragma unroll
                for (int nf = 0; nf < 8; nf++) {
                    accO[nf][2*hh]   *= corr;
                    accO[nf][2*hh+1] *= corr;
                }
            }

            // ---- O += P @ V (P single-pass fp16; V frags straight LDS) ----
            #pragma unroll
            for (int ks = 0; ks < 4; ks++) {
                uint32_t ph[4];
                ph[0] = cvt2h(accS[2*ks][0],   accS[2*ks][1]);
                ph[1] = cvt2h(accS[2*ks][2],   accS[2*ks][3]);
                ph[2] = cvt2h(accS[2*ks+1][0], accS[2*ks+1][1]);
                ph[3] = cvt2h(accS[2*ks+1][2], accS[2*ks+1][3]);
                const int cp = 8 * ks + tq;
                #pragma unroll
                for (int nf = 0; nf < 8; nf++) {
                    const int nb = nf * 8 + g;
                    uint32_t vh[2];
                    vh[0] = Vs[nb * VSTR + cp];
                    vh[1] = Vs[nb * VSTR + cp + 4];
                    mma_f16(accO[nf], ph, vh);
                }
            }
        }
        __syncthreads();   // all reads of stage s done before refill

        if (j + 2 < nkv)
            attn_load_stage(sb + (uint32_t)s * ASTG_W * 4, kp, vt, kv0 + 128, tid);
        CP_COMMIT();
    }

    // ---- write y packed hi/lo [m][kp] (proj A-operand, zero-cvt there) ----
    const int b = bh >> 4, hd = bh & 15;
    #pragma unroll
    for (int hh = 0; hh < 2; hh++) {
        float inv = 1.0f / lrow[hh];
        int t = q0 + wid * 16 + g + hh * 8;
        size_t rowbase = (size_t)(b * T_ + t) * KP2_ + hd * 32;
        #pragma unroll
        for (int nf = 0; nf < 8; nf++) {
            uint32_t ph, pl;
            split2h(accO[nf][2*hh] * inv, accO[nf][2*hh+1] * inv, ph, pl);
            g_yp_h[rowbase + nf * 4 + tq] = ph;
            g_yp_l[rowbase + nf * 4 + tq] = pl;
        }
    }
}

// ---------------------------------------------------------------------------
extern "C" void kernel_launch(void* const* d_in, const int* in_sizes, int n_in,
                              void* d_out, int out_size)
{
    const float* x      = (const float*)d_in[0];
    const float* w_qkv  = (const float*)d_in[1];
    const float* w_proj = (const float*)d_in[2];
    const float* b_proj = (const float*)d_in[3];
    float* out = (float*)d_out;
    (void)in_sizes; (void)n_in; (void)out_size;

    cudaFuncSetAttribute(gemm_f16<0>,
                         cudaFuncAttributeMaxDynamicSharedMemorySize, GEMM_SMEM_BYTES);
    cudaFuncSetAttribute(gemm_f16<1>,
                         cudaFuncAttributeMaxDynamicSharedMemorySize, GEMM_SMEM_BYTES);
    cudaFuncSetAttribute(attn_mma,
                         cudaFuncAttributeMaxDynamicSharedMemorySize, ATTN_SMEM_B);

    rope_table_kernel<<<256, 256>>>();
    convert_x_kernel<<<M_ * K_ / 4 / 256, 256>>>(x);
    convert_w_kernel<0><<<(KP2_ * N3_ / 4) / 256, 256>>>(w_qkv, N3_);
    convert_w_kernel<1><<<(KP2_ * C_  / 4) / 256, 256>>>(w_proj, C_);
    gemm_f16<0><<<dim3(N3_ / 128, M_ / 128), 256, GEMM_SMEM_BYTES>>>(nullptr, nullptr);
    attn_mma<<<dim3(T_ / 128, BH_), 256, ATTN_SMEM_B>>>();
    gemm_f16<1><<<dim3(C_ / 128, M_ / 128), 256, GEMM_SMEM_BYTES>>>(b_proj, out);
}